// round 2
// baseline (speedup 1.0000x reference)
#include <cuda_runtime.h>
#include <cuda_fp16.h>
#include <mma.h>

using namespace nvcuda;

#define HID    1024
#define NHEADS 16
#define DK     64
#define BATCH  2
#define SEQ    2048
#define MTOT   (BATCH*SEQ)   // 4096

// ----------------------------------------------------------------------------
// Scratch (device globals; no allocations allowed)
// hi/lo error-compensated fp16 representation of every MMA operand.
// ----------------------------------------------------------------------------
__device__ __align__(256) __half g_Xhi[3][MTOT*HID];
__device__ __align__(256) __half g_Xlo[3][MTOT*HID];
__device__ __align__(256) __half g_Whi[4][HID*HID];
__device__ __align__(256) __half g_Wlo[4][HID*HID];
__device__ __align__(256) __half g_QKVhi[3][MTOT*HID];  // [b,h,s,d]
__device__ __align__(256) __half g_QKVlo[3][MTOT*HID];
__device__ __align__(256) __half g_AOhi[MTOT*HID];      // [b,s,h*d]
__device__ __align__(256) __half g_AOlo[MTOT*HID];

// ----------------------------------------------------------------------------
// fp32 -> (hi, lo) fp16 split
// ----------------------------------------------------------------------------
__global__ void f2hl_kernel(const float* __restrict__ src, int sel, int n) {
    __half *hi, *lo;
    if (sel < 3) { hi = g_Xhi[sel];   lo = g_Xlo[sel];   }
    else         { hi = g_Whi[sel-3]; lo = g_Wlo[sel-3]; }
    int i = blockIdx.x * blockDim.x + threadIdx.x;
    if (i < n) {
        float x = src[i];
        __half h = __float2half_rn(x);
        hi[i] = h;
        lo[i] = __float2half_rn(x - __half2float(h));
    }
}

// ----------------------------------------------------------------------------
// QKV projection: Y[b,h,s,d] = X[b,s,:] @ W[h*64+d,:]^T   (3-term compensated)
// Block = 128 threads (4 warps), tile 64x64, K-step 64.
// ----------------------------------------------------------------------------
__global__ void __launch_bounds__(128) proj_gemm_kernel() {
    __shared__ __align__(16) char sm[4*64*72*2];  // 36,864 B
    __half* As_hi = (__half*)sm;
    __half* As_lo = As_hi + 64*72;
    __half* Bs_hi = As_lo + 64*72;
    __half* Bs_lo = Bs_hi + 64*72;
    float*  Cs    = (float*)sm;  // overlaid after k-loop (64*68*4 = 17,408 B)

    int z = blockIdx.z;
    const __half* Ahi = g_Xhi[z]; const __half* Alo = g_Xlo[z];
    const __half* Bhi = g_Whi[z]; const __half* Blo = g_Wlo[z];
    __half* Ohi = g_QKVhi[z];     __half* Olo = g_QKVlo[z];

    int m0 = blockIdx.x * 64, n0 = blockIdx.y * 64;
    int t = threadIdx.x, w = t >> 5;

    wmma::fragment<wmma::accumulator,16,16,16,float> acc[4];
    #pragma unroll
    for (int j = 0; j < 4; j++) wmma::fill_fragment(acc[j], 0.0f);

    for (int k0 = 0; k0 < HID; k0 += 64) {
        #pragma unroll
        for (int i = 0; i < 4; i++) {
            int c = t + i*128; int row = c >> 3; int col = (c & 7) * 8;
            size_t ga = (size_t)(m0 + row) * HID + k0 + col;
            size_t gb = (size_t)(n0 + row) * HID + k0 + col;
            *(uint4*)(As_hi + row*72 + col) = *(const uint4*)(Ahi + ga);
            *(uint4*)(As_lo + row*72 + col) = *(const uint4*)(Alo + ga);
            *(uint4*)(Bs_hi + row*72 + col) = *(const uint4*)(Bhi + gb);
            *(uint4*)(Bs_lo + row*72 + col) = *(const uint4*)(Blo + gb);
        }
        __syncthreads();
        #pragma unroll
        for (int kk = 0; kk < 64; kk += 16) {
            wmma::fragment<wmma::matrix_a,16,16,16,__half,wmma::row_major> ah, al;
            wmma::load_matrix_sync(ah, As_hi + w*16*72 + kk, 72);
            wmma::load_matrix_sync(al, As_lo + w*16*72 + kk, 72);
            #pragma unroll
            for (int j = 0; j < 4; j++) {
                wmma::fragment<wmma::matrix_b,16,16,16,__half,wmma::col_major> bh, bl;
                wmma::load_matrix_sync(bh, Bs_hi + j*16*72 + kk, 72);
                wmma::load_matrix_sync(bl, Bs_lo + j*16*72 + kk, 72);
                wmma::mma_sync(acc[j], ah, bh, acc[j]);
                wmma::mma_sync(acc[j], ah, bl, acc[j]);
                wmma::mma_sync(acc[j], al, bh, acc[j]);
            }
        }
        __syncthreads();
    }

    #pragma unroll
    for (int j = 0; j < 4; j++)
        wmma::store_matrix_sync(Cs + w*16*68 + j*16, acc[j], 68, wmma::mem_row_major);
    __syncthreads();

    int hd = blockIdx.y;  // tile width == DK, so one head per n-tile
    #pragma unroll
    for (int i = 0; i < 32; i++) {
        int idx = t + i*128;
        int r = idx >> 6, c = idx & 63;
        int rg = m0 + r;
        int b = rg >> 11, s = rg & (SEQ - 1);
        float v = Cs[r*68 + c];
        __half hv = __float2half_rn(v);
        size_t o = (((size_t)b * NHEADS + hd) * SEQ + s) * DK + c;
        Ohi[o] = hv;
        Olo[o] = __float2half_rn(v - __half2float(hv));
    }
}

// ----------------------------------------------------------------------------
// Output projection: out[b*s, :] = AO @ Wo^T, fp32 direct store (3-term)
// ----------------------------------------------------------------------------
__global__ void __launch_bounds__(128) oproj_gemm_kernel(float* __restrict__ out) {
    __shared__ __align__(16) char sm[4*64*72*2];
    __half* As_hi = (__half*)sm;
    __half* As_lo = As_hi + 64*72;
    __half* Bs_hi = As_lo + 64*72;
    __half* Bs_lo = Bs_hi + 64*72;

    const __half* Ahi = g_AOhi; const __half* Alo = g_AOlo;
    const __half* Bhi = g_Whi[3]; const __half* Blo = g_Wlo[3];

    int m0 = blockIdx.x * 64, n0 = blockIdx.y * 64;
    int t = threadIdx.x, w = t >> 5;

    wmma::fragment<wmma::accumulator,16,16,16,float> acc[4];
    #pragma unroll
    for (int j = 0; j < 4; j++) wmma::fill_fragment(acc[j], 0.0f);

    for (int k0 = 0; k0 < HID; k0 += 64) {
        #pragma unroll
        for (int i = 0; i < 4; i++) {
            int c = t + i*128; int row = c >> 3; int col = (c & 7) * 8;
            size_t ga = (size_t)(m0 + row) * HID + k0 + col;
            size_t gb = (size_t)(n0 + row) * HID + k0 + col;
            *(uint4*)(As_hi + row*72 + col) = *(const uint4*)(Ahi + ga);
            *(uint4*)(As_lo + row*72 + col) = *(const uint4*)(Alo + ga);
            *(uint4*)(Bs_hi + row*72 + col) = *(const uint4*)(Bhi + gb);
            *(uint4*)(Bs_lo + row*72 + col) = *(const uint4*)(Blo + gb);
        }
        __syncthreads();
        #pragma unroll
        for (int kk = 0; kk < 64; kk += 16) {
            wmma::fragment<wmma::matrix_a,16,16,16,__half,wmma::row_major> ah, al;
            wmma::load_matrix_sync(ah, As_hi + w*16*72 + kk, 72);
            wmma::load_matrix_sync(al, As_lo + w*16*72 + kk, 72);
            #pragma unroll
            for (int j = 0; j < 4; j++) {
                wmma::fragment<wmma::matrix_b,16,16,16,__half,wmma::col_major> bh, bl;
                wmma::load_matrix_sync(bh, Bs_hi + j*16*72 + kk, 72);
                wmma::load_matrix_sync(bl, Bs_lo + j*16*72 + kk, 72);
                wmma::mma_sync(acc[j], ah, bh, acc[j]);
                wmma::mma_sync(acc[j], ah, bl, acc[j]);
                wmma::mma_sync(acc[j], al, bh, acc[j]);
            }
        }
        __syncthreads();
    }
    #pragma unroll
    for (int j = 0; j < 4; j++)
        wmma::store_matrix_sync(out + (size_t)(m0 + w*16) * HID + n0 + j*16,
                                acc[j], HID, wmma::mem_row_major);
}

// ----------------------------------------------------------------------------
// Flash attention: 64-row Q tile per block, online softmax, WMMA QK^T & PV.
// Dynamic smem ≈ 98 KB.
// ----------------------------------------------------------------------------
#define ATTN_SMEM (7*64*72*2 + 2*64*68*4 + 3*64*4)   // 100,096 B

__global__ void __launch_bounds__(128) attn_kernel(const unsigned char* __restrict__ mask) {
    extern __shared__ __align__(16) char dsm[];
    __half* Qhi = (__half*)dsm;
    __half* Qlo = Qhi + 64*72;
    __half* Khi = Qlo + 64*72;
    __half* Klo = Khi + 64*72;
    __half* Vhi = Klo + 64*72;
    __half* Vlo = Vhi + 64*72;
    __half* Ps  = Vlo + 64*72;
    float*  Ss  = (float*)(Ps + 64*72);
    float*  Os  = Ss + 64*68;
    float*  mrow = Os + 64*68;
    float*  lrow = mrow + 64;
    float*  efs  = lrow + 64;

    int qt = blockIdx.x, hd = blockIdx.y, b = blockIdx.z;
    int q0 = qt * 64;
    size_t base = ((size_t)b * NHEADS + hd) * SEQ;
    const __half* Qhi_g = g_QKVhi[0] + (base + q0) * DK;
    const __half* Qlo_g = g_QKVlo[0] + (base + q0) * DK;
    const __half* Khi_g = g_QKVhi[1] + base * DK;
    const __half* Klo_g = g_QKVlo[1] + base * DK;
    const __half* Vhi_g = g_QKVhi[2] + base * DK;
    const __half* Vlo_g = g_QKVlo[2] + base * DK;

    int t = threadIdx.x, w = t >> 5;
    const __half2 sc2 = __float2half2_rn(0.125f);  // 1/sqrt(64), exact pow2

    // Load Q tile with scale folded in (exact: power of two)
    #pragma unroll
    for (int i = 0; i < 4; i++) {
        int c = t + i*128; int row = c >> 3; int col = (c & 7) * 8;
        uint4 vh_ = *(const uint4*)(Qhi_g + row*DK + col);
        uint4 vl_ = *(const uint4*)(Qlo_g + row*DK + col);
        __half2* ph = (__half2*)&vh_;
        __half2* pl = (__half2*)&vl_;
        #pragma unroll
        for (int u = 0; u < 4; u++) { ph[u] = __hmul2(ph[u], sc2); pl[u] = __hmul2(pl[u], sc2); }
        *(uint4*)(Qhi + row*72 + col) = vh_;
        *(uint4*)(Qlo + row*72 + col) = vl_;
    }
    #pragma unroll
    for (int i = 0; i < 32; i++) { int idx = t + i*128; Os[(idx>>6)*68 + (idx&63)] = 0.0f; }
    if (t < 64) { mrow[t] = -1e30f; lrow[t] = 0.0f; }
    __syncthreads();

    for (int j0 = 0; j0 < SEQ; j0 += 64) {
        // Load K, V tiles
        #pragma unroll
        for (int i = 0; i < 4; i++) {
            int c = t + i*128; int row = c >> 3; int col = (c & 7) * 8;
            size_t g = (size_t)(j0 + row) * DK + col;
            *(uint4*)(Khi + row*72 + col) = *(const uint4*)(Khi_g + g);
            *(uint4*)(Klo + row*72 + col) = *(const uint4*)(Klo_g + g);
            *(uint4*)(Vhi + row*72 + col) = *(const uint4*)(Vhi_g + g);
            *(uint4*)(Vlo + row*72 + col) = *(const uint4*)(Vlo_g + g);
        }
        __syncthreads();

        // S = (Q*scale) @ K^T  (3-term compensated)
        {
            wmma::fragment<wmma::accumulator,16,16,16,float> sacc[4];
            #pragma unroll
            for (int j = 0; j < 4; j++) wmma::fill_fragment(sacc[j], 0.0f);
            #pragma unroll
            for (int kk = 0; kk < 64; kk += 16) {
                wmma::fragment<wmma::matrix_a,16,16,16,__half,wmma::row_major> ah, al;
                wmma::load_matrix_sync(ah, Qhi + w*16*72 + kk, 72);
                wmma::load_matrix_sync(al, Qlo + w*16*72 + kk, 72);
                #pragma unroll
                for (int j = 0; j < 4; j++) {
                    wmma::fragment<wmma::matrix_b,16,16,16,__half,wmma::col_major> bh, bl;
                    wmma::load_matrix_sync(bh, Khi + j*16*72 + kk, 72);
                    wmma::load_matrix_sync(bl, Klo + j*16*72 + kk, 72);
                    wmma::mma_sync(sacc[j], ah, bh, sacc[j]);
                    wmma::mma_sync(sacc[j], ah, bl, sacc[j]);
                    wmma::mma_sync(sacc[j], al, bh, sacc[j]);
                }
            }
            #pragma unroll
            for (int j = 0; j < 4; j++)
                wmma::store_matrix_sync(Ss + w*16*68 + j*16, sacc[j], 68, wmma::mem_row_major);
        }
        __syncthreads();

        // Online softmax (2 threads per row, 32 cols each)
        {
            int r = t >> 1, jh = t & 1;
            const unsigned char* mp = mask + ((size_t)b*SEQ + q0 + r) * SEQ + j0 + jh*32;
            float vals[32];
            float mx = -1e30f;
            #pragma unroll
            for (int jj = 0; jj < 32; jj++) {
                float x = Ss[r*68 + jh*32 + jj];
                if (mp[jj]) x = -1e9f;
                vals[jj] = x;
                mx = fmaxf(mx, x);
            }
            mx = fmaxf(mx, __shfl_xor_sync(0xffffffffu, mx, 1));
            float mold = mrow[r];
            float mnew = fmaxf(mold, mx);
            float sum = 0.0f;
            #pragma unroll
            for (int jj = 0; jj < 32; jj++) {
                float p = __expf(vals[jj] - mnew);
                sum += p;
                Ps[r*72 + jh*32 + jj] = __float2half_rn(p);
            }
            sum += __shfl_xor_sync(0xffffffffu, sum, 1);
            if (jh == 0) {
                float ef = __expf(mold - mnew);   // -> 0 on first tile
                lrow[r] = lrow[r] * ef + sum;
                mrow[r] = mnew;
                efs[r] = ef;
            }
        }
        __syncthreads();

        // Rescale O accumulator
        #pragma unroll
        for (int i = 0; i < 32; i++) {
            int idx = t + i*128; int r = idx >> 6, c = idx & 63;
            Os[r*68 + c] *= efs[r];
        }
        __syncthreads();

        // O += P @ V  (V compensated: 2-term)
        {
            wmma::fragment<wmma::accumulator,16,16,16,float> oacc[4];
            #pragma unroll
            for (int j = 0; j < 4; j++)
                wmma::load_matrix_sync(oacc[j], Os + w*16*68 + j*16, 68, wmma::mem_row_major);
            #pragma unroll
            for (int kk = 0; kk < 64; kk += 16) {
                wmma::fragment<wmma::matrix_a,16,16,16,__half,wmma::row_major> pf;
                wmma::load_matrix_sync(pf, Ps + w*16*72 + kk, 72);
                #pragma unroll
                for (int j = 0; j < 4; j++) {
                    wmma::fragment<wmma::matrix_b,16,16,16,__half,wmma::row_major> bh, bl;
                    wmma::load_matrix_sync(bh, Vhi + kk*72 + j*16, 72);
                    wmma::load_matrix_sync(bl, Vlo + kk*72 + j*16, 72);
                    wmma::mma_sync(oacc[j], pf, bh, oacc[j]);
                    wmma::mma_sync(oacc[j], pf, bl, oacc[j]);
                }
            }
            #pragma unroll
            for (int j = 0; j < 4; j++)
                wmma::store_matrix_sync(Os + w*16*68 + j*16, oacc[j], 68, wmma::mem_row_major);
        }
        __syncthreads();
    }

    // Epilogue: normalize & write [b, s, h*64+d] as hi/lo
    #pragma unroll
    for (int i = 0; i < 32; i++) {
        int idx = t + i*128; int r = idx >> 6, c = idx & 63;
        float o = Os[r*68 + c] / lrow[r];
        __half hv = __float2half_rn(o);
        size_t oo = ((size_t)b*SEQ + q0 + r) * HID + hd*DK + c;
        g_AOhi[oo] = hv;
        g_AOlo[oo] = __float2half_rn(o - __half2float(hv));
    }
}

// ----------------------------------------------------------------------------
// Launch
// ----------------------------------------------------------------------------
extern "C" void kernel_launch(void* const* d_in, const int* in_sizes, int n_in,
                              void* d_out, int out_size) {
    const float* q    = (const float*)d_in[0];
    const float* k    = (const float*)d_in[1];
    const float* v    = (const float*)d_in[2];
    const unsigned char* mask = (const unsigned char*)d_in[3];
    const float* Wq   = (const float*)d_in[4];
    const float* Wk   = (const float*)d_in[5];
    const float* Wv   = (const float*)d_in[6];
    const float* Wo   = (const float*)d_in[7];
    float* out = (float*)d_out;

    const int nx = MTOT * HID;  // 4,194,304
    const int nw = HID * HID;   // 1,048,576

    f2hl_kernel<<<nx/256, 256>>>(q,  0, nx);
    f2hl_kernel<<<nx/256, 256>>>(k,  1, nx);
    f2hl_kernel<<<nx/256, 256>>>(v,  2, nx);
    f2hl_kernel<<<nw/256, 256>>>(Wq, 3, nw);
    f2hl_kernel<<<nw/256, 256>>>(Wk, 4, nw);
    f2hl_kernel<<<nw/256, 256>>>(Wv, 5, nw);
    f2hl_kernel<<<nw/256, 256>>>(Wo, 6, nw);

    proj_gemm_kernel<<<dim3(MTOT/64, HID/64, 3), 128>>>();

    cudaFuncSetAttribute(attn_kernel, cudaFuncAttributeMaxDynamicSharedMemorySize, ATTN_SMEM);
    attn_kernel<<<dim3(SEQ/64, NHEADS, BATCH), 128, ATTN_SMEM>>>(mask);

    oproj_gemm_kernel<<<dim3(MTOT/64, HID/64), 128>>>(out);
}

// round 3
// speedup vs baseline: 1.0594x; 1.0594x over previous
#include <cuda_runtime.h>
#include <cuda_fp16.h>
#include <mma.h>
#include <stdint.h>

using namespace nvcuda;

#define HID    1024
#define NHEADS 16
#define DK     64
#define BATCH  2
#define SEQ    2048
#define MTOT   (BATCH*SEQ)   // 4096

// ----------------------------------------------------------------------------
// Scratch (device globals)
// ----------------------------------------------------------------------------
__device__ __align__(256) __half g_Xhi[3][MTOT*HID];
__device__ __align__(256) __half g_Xlo[3][MTOT*HID];
__device__ __align__(256) __half g_Whi[4][HID*HID];
__device__ __align__(256) __half g_Wlo[4][HID*HID];
__device__ __align__(256) __half g_QKVhi[3][MTOT*HID];  // [b,h,s,d]
__device__ __align__(256) __half g_QKVlo[3][MTOT*HID];
__device__ __align__(256) __half g_AOhi[MTOT*HID];      // [b,s,h*d]
__device__ __align__(256) __half g_AOlo[MTOT*HID];

// ----------------------------------------------------------------------------
// Fused fp32 -> (hi,lo) fp16 split for all 7 input tensors (one launch)
// ----------------------------------------------------------------------------
__global__ void __launch_bounds__(256) f2hl_all(
    const float* __restrict__ q, const float* __restrict__ k,
    const float* __restrict__ v, const float* __restrict__ wq,
    const float* __restrict__ wk, const float* __restrict__ wv,
    const float* __restrict__ wo)
{
    int sel = blockIdx.y;
    const float* src; __half* hi; __half* lo; int n;
    switch (sel) {
        case 0: src=q;  hi=g_Xhi[0]; lo=g_Xlo[0]; n=MTOT*HID; break;
        case 1: src=k;  hi=g_Xhi[1]; lo=g_Xlo[1]; n=MTOT*HID; break;
        case 2: src=v;  hi=g_Xhi[2]; lo=g_Xlo[2]; n=MTOT*HID; break;
        case 3: src=wq; hi=g_Whi[0]; lo=g_Wlo[0]; n=HID*HID;  break;
        case 4: src=wk; hi=g_Whi[1]; lo=g_Wlo[1]; n=HID*HID;  break;
        case 5: src=wv; hi=g_Whi[2]; lo=g_Wlo[2]; n=HID*HID;  break;
        default:src=wo; hi=g_Whi[3]; lo=g_Wlo[3]; n=HID*HID;  break;
    }
    int i = (blockIdx.x * 256 + threadIdx.x) * 4;
    if (i >= n) return;
    float4 x = *(const float4*)(src + i);
    __half h0 = __float2half_rn(x.x), h1 = __float2half_rn(x.y);
    __half h2 = __float2half_rn(x.z), h3 = __float2half_rn(x.w);
    ((__half2*)(hi + i))[0] = __halves2half2(h0, h1);
    ((__half2*)(hi + i))[1] = __halves2half2(h2, h3);
    ((__half2*)(lo + i))[0] = __halves2half2(__float2half_rn(x.x - __half2float(h0)),
                                             __float2half_rn(x.y - __half2float(h1)));
    ((__half2*)(lo + i))[1] = __halves2half2(__float2half_rn(x.z - __half2float(h2)),
                                             __float2half_rn(x.w - __half2float(h3)));
}

// ----------------------------------------------------------------------------
// QKV projection: Y[b,h,s,d] = X @ W^T   (3-term compensated)
// 256 threads, tile 128x128, k-step 64. Dynamic smem 73,728 B.
// ----------------------------------------------------------------------------
__global__ void __launch_bounds__(256,2) proj_gemm_kernel() {
    extern __shared__ __align__(16) char dsm[];
    __half* Ah = (__half*)dsm;           // 128*72
    __half* Al = Ah + 128*72;
    __half* Bh = Al + 128*72;
    __half* Bl = Bh + 128*72;
    float*  Cs = (float*)dsm;            // 128*132 overlay

    int z = blockIdx.z;
    const __half* Agh = g_Xhi[z]; const __half* Agl = g_Xlo[z];
    const __half* Bgh = g_Whi[z]; const __half* Bgl = g_Wlo[z];
    __half* Ohi = g_QKVhi[z];     __half* Olo = g_QKVlo[z];

    int m0 = blockIdx.x * 128, n0 = blockIdx.y * 128;
    int t = threadIdx.x, w = t >> 5;
    int wm = w & 3, wn = w >> 2;

    wmma::fragment<wmma::accumulator,16,16,16,float> acc[2][4];
    #pragma unroll
    for (int mi = 0; mi < 2; mi++)
        #pragma unroll
        for (int j = 0; j < 4; j++) wmma::fill_fragment(acc[mi][j], 0.0f);

    for (int k0 = 0; k0 < HID; k0 += 64) {
        #pragma unroll
        for (int i = 0; i < 4; i++) {
            int idx = t + i*256; int row = idx >> 3; int col = (idx & 7) * 8;
            size_t ga = (size_t)(m0 + row) * HID + k0 + col;
            size_t gb = (size_t)(n0 + row) * HID + k0 + col;
            *(uint4*)(Ah + row*72 + col) = *(const uint4*)(Agh + ga);
            *(uint4*)(Al + row*72 + col) = *(const uint4*)(Agl + ga);
            *(uint4*)(Bh + row*72 + col) = *(const uint4*)(Bgh + gb);
            *(uint4*)(Bl + row*72 + col) = *(const uint4*)(Bgl + gb);
        }
        __syncthreads();
        #pragma unroll
        for (int kk = 0; kk < 64; kk += 16) {
            wmma::fragment<wmma::matrix_a,16,16,16,__half,wmma::row_major> ah2[2], al2[2];
            #pragma unroll
            for (int mi = 0; mi < 2; mi++) {
                wmma::load_matrix_sync(ah2[mi], Ah + (wm*32 + mi*16)*72 + kk, 72);
                wmma::load_matrix_sync(al2[mi], Al + (wm*32 + mi*16)*72 + kk, 72);
            }
            #pragma unroll
            for (int j = 0; j < 4; j++) {
                wmma::fragment<wmma::matrix_b,16,16,16,__half,wmma::col_major> bh2, bl2;
                wmma::load_matrix_sync(bh2, Bh + (wn*64 + j*16)*72 + kk, 72);
                wmma::load_matrix_sync(bl2, Bl + (wn*64 + j*16)*72 + kk, 72);
                #pragma unroll
                for (int mi = 0; mi < 2; mi++) {
                    wmma::mma_sync(acc[mi][j], ah2[mi], bh2, acc[mi][j]);
                    wmma::mma_sync(acc[mi][j], ah2[mi], bl2, acc[mi][j]);
                    wmma::mma_sync(acc[mi][j], al2[mi], bh2, acc[mi][j]);
                }
            }
        }
        __syncthreads();
    }

    #pragma unroll
    for (int mi = 0; mi < 2; mi++)
        #pragma unroll
        for (int j = 0; j < 4; j++)
            wmma::store_matrix_sync(Cs + (wm*32 + mi*16)*132 + wn*64 + j*16,
                                    acc[mi][j], 132, wmma::mem_row_major);
    __syncthreads();

    for (int i = 0; i < 64; i++) {
        int idx = t + i*256; int r = idx >> 7; int c = idx & 127;
        float v0 = Cs[r*132 + c];
        int head = blockIdx.y*2 + (c >> 6); int d = c & 63;
        int rg = m0 + r; int b = rg >> 11; int s = rg & (SEQ-1);
        size_t o = (((size_t)b * NHEADS + head) * SEQ + s) * DK + d;
        __half hv = __float2half_rn(v0);
        Ohi[o] = hv;
        Olo[o] = __float2half_rn(v0 - __half2float(hv));
    }
}

// ----------------------------------------------------------------------------
// Output projection: out = AO @ Wo^T   (3-term, fp32 direct store)
// ----------------------------------------------------------------------------
__global__ void __launch_bounds__(256,2) oproj_gemm_kernel(float* __restrict__ out) {
    extern __shared__ __align__(16) char dsm[];
    __half* Ah = (__half*)dsm;
    __half* Al = Ah + 128*72;
    __half* Bh = Al + 128*72;
    __half* Bl = Bh + 128*72;

    const __half* Agh = g_AOhi; const __half* Agl = g_AOlo;
    const __half* Bgh = g_Whi[3]; const __half* Bgl = g_Wlo[3];

    int m0 = blockIdx.x * 128, n0 = blockIdx.y * 128;
    int t = threadIdx.x, w = t >> 5;
    int wm = w & 3, wn = w >> 2;

    wmma::fragment<wmma::accumulator,16,16,16,float> acc[2][4];
    #pragma unroll
    for (int mi = 0; mi < 2; mi++)
        #pragma unroll
        for (int j = 0; j < 4; j++) wmma::fill_fragment(acc[mi][j], 0.0f);

    for (int k0 = 0; k0 < HID; k0 += 64) {
        #pragma unroll
        for (int i = 0; i < 4; i++) {
            int idx = t + i*256; int row = idx >> 3; int col = (idx & 7) * 8;
            size_t ga = (size_t)(m0 + row) * HID + k0 + col;
            size_t gb = (size_t)(n0 + row) * HID + k0 + col;
            *(uint4*)(Ah + row*72 + col) = *(const uint4*)(Agh + ga);
            *(uint4*)(Al + row*72 + col) = *(const uint4*)(Agl + ga);
            *(uint4*)(Bh + row*72 + col) = *(const uint4*)(Bgh + gb);
            *(uint4*)(Bl + row*72 + col) = *(const uint4*)(Bgl + gb);
        }
        __syncthreads();
        #pragma unroll
        for (int kk = 0; kk < 64; kk += 16) {
            wmma::fragment<wmma::matrix_a,16,16,16,__half,wmma::row_major> ah2[2], al2[2];
            #pragma unroll
            for (int mi = 0; mi < 2; mi++) {
                wmma::load_matrix_sync(ah2[mi], Ah + (wm*32 + mi*16)*72 + kk, 72);
                wmma::load_matrix_sync(al2[mi], Al + (wm*32 + mi*16)*72 + kk, 72);
            }
            #pragma unroll
            for (int j = 0; j < 4; j++) {
                wmma::fragment<wmma::matrix_b,16,16,16,__half,wmma::col_major> bh2, bl2;
                wmma::load_matrix_sync(bh2, Bh + (wn*64 + j*16)*72 + kk, 72);
                wmma::load_matrix_sync(bl2, Bl + (wn*64 + j*16)*72 + kk, 72);
                #pragma unroll
                for (int mi = 0; mi < 2; mi++) {
                    wmma::mma_sync(acc[mi][j], ah2[mi], bh2, acc[mi][j]);
                    wmma::mma_sync(acc[mi][j], ah2[mi], bl2, acc[mi][j]);
                    wmma::mma_sync(acc[mi][j], al2[mi], bh2, acc[mi][j]);
                }
            }
        }
        __syncthreads();
    }
    #pragma unroll
    for (int mi = 0; mi < 2; mi++)
        #pragma unroll
        for (int j = 0; j < 4; j++)
            wmma::store_matrix_sync(out + (size_t)(m0 + wm*32 + mi*16) * HID + n0 + wn*64 + j*16,
                                    acc[mi][j], HID, wmma::mem_row_major);
}

// ----------------------------------------------------------------------------
// Flash attention, raw mma.m16n8k16, register-resident S/O, warp-local softmax
// ----------------------------------------------------------------------------
__device__ __forceinline__ void mma_f16(float* c, const uint32_t* a, const uint32_t* b) {
    asm volatile(
        "mma.sync.aligned.m16n8k16.row.col.f32.f16.f16.f32 "
        "{%0,%1,%2,%3}, {%4,%5,%6,%7}, {%8,%9}, {%0,%1,%2,%3};"
        : "+f"(c[0]), "+f"(c[1]), "+f"(c[2]), "+f"(c[3])
        : "r"(a[0]), "r"(a[1]), "r"(a[2]), "r"(a[3]), "r"(b[0]), "r"(b[1]));
}

__device__ __forceinline__ uint32_t pk(float a, float b) {
    __half2 h = __floats2half2_rn(a, b);
    return *(uint32_t*)&h;
}

__global__ void __launch_bounds__(128,2) attn_kernel(const unsigned char* __restrict__ mask) {
    __shared__ __align__(16) __half Kh[64*72], Kl[64*72], Vth[64*72], Vtl[64*72];
    __shared__ __align__(16) unsigned char Msk[64*64];

    int t = threadIdx.x, lane = t & 31, w = t >> 5;
    int gr = lane >> 2, qp = lane & 3;
    int qt = blockIdx.x, hd = blockIdx.y, b = blockIdx.z;
    int q0 = qt * 64;
    size_t base = ((size_t)b * NHEADS + hd) * SEQ;
    const __half* Qh_g = g_QKVhi[0] + (base + q0) * DK;
    const __half* Ql_g = g_QKVlo[0] + (base + q0) * DK;
    const __half* Kh_g = g_QKVhi[1] + base * DK;
    const __half* Kl_g = g_QKVlo[1] + base * DK;
    const __half* Vh_g = g_QKVhi[2] + base * DK;
    const __half* Vl_g = g_QKVlo[2] + base * DK;

    int r0 = w*16 + gr;     // tile-local Q row for acc half 0
    int r1 = r0 + 8;        // acc half 1

    // Q fragments (hi/lo), scale 0.125 folded in (exact pow2)
    const __half2 sc = __float2half2_rn(0.125f);
    uint32_t qa[2][4][4];
    #pragma unroll
    for (int kc = 0; kc < 4; kc++) {
        int cb = kc*16 + qp*2;
        __half2 v;
        v = __hmul2(*(const __half2*)(Qh_g + r0*DK + cb),     sc); qa[0][kc][0] = *(uint32_t*)&v;
        v = __hmul2(*(const __half2*)(Qh_g + r1*DK + cb),     sc); qa[0][kc][1] = *(uint32_t*)&v;
        v = __hmul2(*(const __half2*)(Qh_g + r0*DK + cb + 8), sc); qa[0][kc][2] = *(uint32_t*)&v;
        v = __hmul2(*(const __half2*)(Qh_g + r1*DK + cb + 8), sc); qa[0][kc][3] = *(uint32_t*)&v;
        v = __hmul2(*(const __half2*)(Ql_g + r0*DK + cb),     sc); qa[1][kc][0] = *(uint32_t*)&v;
        v = __hmul2(*(const __half2*)(Ql_g + r1*DK + cb),     sc); qa[1][kc][1] = *(uint32_t*)&v;
        v = __hmul2(*(const __half2*)(Ql_g + r0*DK + cb + 8), sc); qa[1][kc][2] = *(uint32_t*)&v;
        v = __hmul2(*(const __half2*)(Ql_g + r1*DK + cb + 8), sc); qa[1][kc][3] = *(uint32_t*)&v;
    }

    float o[8][4];
    #pragma unroll
    for (int n = 0; n < 8; n++) { o[n][0]=0.f; o[n][1]=0.f; o[n][2]=0.f; o[n][3]=0.f; }
    float m0v = -1e30f, m1v = -1e30f, l0 = 0.f, l1 = 0.f;

    for (int j0 = 0; j0 < SEQ; j0 += 64) {
        // Cooperative loads: K hi/lo row-major [j][d]; V hi/lo transposed [d][j^sw]
        #pragma unroll
        for (int i = 0; i < 4; i++) {
            int idx = t + i*128; int row = idx >> 3; int col = (idx & 7) * 8;
            size_t g = (size_t)(j0 + row) * DK + col;
            *(uint4*)(Kh + row*72 + col) = *(const uint4*)(Kh_g + g);
            *(uint4*)(Kl + row*72 + col) = *(const uint4*)(Kl_g + g);
            uint4 vh = *(const uint4*)(Vh_g + g);
            uint4 vl = *(const uint4*)(Vl_g + g);
            const __half* ph = (const __half*)&vh;
            const __half* pl = (const __half*)&vl;
            #pragma unroll
            for (int u = 0; u < 8; u++) {
                int d = col + u; int sw = ((d >> 3) & 7) << 1;
                Vth[d*72 + (row ^ sw)] = ph[u];
                Vtl[d*72 + (row ^ sw)] = pl[u];
            }
        }
        #pragma unroll
        for (int i = 0; i < 2; i++) {
            int idx = t + i*128; int rl = idx >> 2, cl = (idx & 3) * 16;
            *(uint4*)(Msk + rl*64 + cl) =
                *(const uint4*)(mask + ((size_t)b*SEQ + q0 + rl) * SEQ + j0 + cl);
        }
        __syncthreads();

        // S = (Q*sc) @ K^T, 3-term compensated
        float s[8][4];
        #pragma unroll
        for (int n = 0; n < 8; n++) { s[n][0]=0.f; s[n][1]=0.f; s[n][2]=0.f; s[n][3]=0.f; }
        #pragma unroll
        for (int kc = 0; kc < 4; kc++) {
            #pragma unroll
            for (int n = 0; n < 8; n++) {
                int nr = n*8 + gr;
                uint32_t bh[2], bl[2];
                bh[0] = *(const uint32_t*)(Kh + nr*72 + kc*16 + qp*2);
                bh[1] = *(const uint32_t*)(Kh + nr*72 + kc*16 + qp*2 + 8);
                bl[0] = *(const uint32_t*)(Kl + nr*72 + kc*16 + qp*2);
                bl[1] = *(const uint32_t*)(Kl + nr*72 + kc*16 + qp*2 + 8);
                mma_f16(s[n], qa[0][kc], bh);
                mma_f16(s[n], qa[0][kc], bl);
                mma_f16(s[n], qa[1][kc], bh);
            }
        }

        // Mask + warp-local online softmax
        const unsigned char* mr0 = Msk + r0*64;
        const unsigned char* mr1 = Msk + r1*64;
        float mx0 = -1e30f, mx1 = -1e30f;
        #pragma unroll
        for (int n = 0; n < 8; n++) {
            #pragma unroll
            for (int e = 0; e < 2; e++) {
                int c = n*8 + qp*2 + e;
                if (mr0[c]) s[n][e]   = -1e9f;
                if (mr1[c]) s[n][2+e] = -1e9f;
                mx0 = fmaxf(mx0, s[n][e]);
                mx1 = fmaxf(mx1, s[n][2+e]);
            }
        }
        mx0 = fmaxf(mx0, __shfl_xor_sync(0xffffffffu, mx0, 1));
        mx0 = fmaxf(mx0, __shfl_xor_sync(0xffffffffu, mx0, 2));
        mx1 = fmaxf(mx1, __shfl_xor_sync(0xffffffffu, mx1, 1));
        mx1 = fmaxf(mx1, __shfl_xor_sync(0xffffffffu, mx1, 2));
        float mn0 = fmaxf(m0v, mx0), mn1 = fmaxf(m1v, mx1);

        float sum0 = 0.f, sum1 = 0.f;
        uint32_t pa[4][4];
        #pragma unroll
        for (int n = 0; n < 8; n++) {
            float p0 = __expf(s[n][0] - mn0);
            float p1 = __expf(s[n][1] - mn0);
            float p2 = __expf(s[n][2] - mn1);
            float p3 = __expf(s[n][3] - mn1);
            sum0 += p0 + p1; sum1 += p2 + p3;
            int kc = n >> 1, h = (n & 1) * 2;
            pa[kc][h]     = pk(p0, p1);
            pa[kc][h + 1] = pk(p2, p3);
        }
        sum0 += __shfl_xor_sync(0xffffffffu, sum0, 1);
        sum0 += __shfl_xor_sync(0xffffffffu, sum0, 2);
        sum1 += __shfl_xor_sync(0xffffffffu, sum1, 1);
        sum1 += __shfl_xor_sync(0xffffffffu, sum1, 2);

        float ef0 = __expf(m0v - mn0), ef1 = __expf(m1v - mn1);
        l0 = l0*ef0 + sum0; l1 = l1*ef1 + sum1;
        m0v = mn0; m1v = mn1;
        #pragma unroll
        for (int n = 0; n < 8; n++) {
            o[n][0] *= ef0; o[n][1] *= ef0; o[n][2] *= ef1; o[n][3] *= ef1;
        }

        // O += P @ V  (V 2-term compensated)
        #pragma unroll
        for (int kc = 0; kc < 4; kc++) {
            #pragma unroll
            for (int n = 0; n < 8; n++) {
                int nd = n*8 + gr; int sw = ((nd >> 3) & 7) << 1;
                int jb = kc*16 + qp*2;
                uint32_t bvh[2], bvl[2];
                bvh[0] = *(const uint32_t*)(Vth + nd*72 + (jb ^ sw));
                bvh[1] = *(const uint32_t*)(Vth + nd*72 + ((jb + 8) ^ sw));
                bvl[0] = *(const uint32_t*)(Vtl + nd*72 + (jb ^ sw));
                bvl[1] = *(const uint32_t*)(Vtl + nd*72 + ((jb + 8) ^ sw));
                mma_f16(o[n], pa[kc], bvh);
                mma_f16(o[n], pa[kc], bvl);
            }
        }
        __syncthreads();
    }

    // Epilogue: normalize, split hi/lo, write [b,s,h*64+d]
    float inv0 = 1.0f / l0, inv1 = 1.0f / l1;
    #pragma unroll
    for (int n = 0; n < 8; n++) {
        int col = n*8 + qp*2;
        float a0 = o[n][0]*inv0, a1 = o[n][1]*inv0;
        float b0 = o[n][2]*inv1, b1 = o[n][3]*inv1;
        __half h00 = __float2half_rn(a0), h01 = __float2half_rn(a1);
        __half h10 = __float2half_rn(b0), h11 = __float2half_rn(b1);
        size_t off0 = ((size_t)b*SEQ + q0 + r0) * HID + hd*DK + col;
        size_t off1 = ((size_t)b*SEQ + q0 + r1) * HID + hd*DK + col;
        *(__half2*)(g_AOhi + off0) = __halves2half2(h00, h01);
        *(__half2*)(g_AOhi + off1) = __halves2half2(h10, h11);
        *(__half2*)(g_AOlo + off0) = __halves2half2(
            __float2half_rn(a0 - __half2float(h00)), __float2half_rn(a1 - __half2float(h01)));
        *(__half2*)(g_AOlo + off1) = __halves2half2(
            __float2half_rn(b0 - __half2float(h10)), __float2half_rn(b1 - __half2float(h11)));
    }
}

// ----------------------------------------------------------------------------
// Launch
// ----------------------------------------------------------------------------
extern "C" void kernel_launch(void* const* d_in, const int* in_sizes, int n_in,
                              void* d_out, int out_size) {
    const float* q    = (const float*)d_in[0];
    const float* k    = (const float*)d_in[1];
    const float* v    = (const float*)d_in[2];
    const unsigned char* mask = (const unsigned char*)d_in[3];
    const float* Wq   = (const float*)d_in[4];
    const float* Wk   = (const float*)d_in[5];
    const float* Wv   = (const float*)d_in[6];
    const float* Wo   = (const float*)d_in[7];
    float* out = (float*)d_out;

    const int GEMM_SMEM = 4 * 128 * 72 * 2;  // 73,728 B
    cudaFuncSetAttribute(proj_gemm_kernel,  cudaFuncAttributeMaxDynamicSharedMemorySize, GEMM_SMEM);
    cudaFuncSetAttribute(oproj_gemm_kernel, cudaFuncAttributeMaxDynamicSharedMemorySize, GEMM_SMEM);

    f2hl_all<<<dim3(MTOT*HID/(256*4), 7), 256>>>(q, k, v, Wq, Wk, Wv, Wo);
    proj_gemm_kernel<<<dim3(MTOT/128, HID/128, 3), 256, GEMM_SMEM>>>();
    attn_kernel<<<dim3(SEQ/64, NHEADS, BATCH), 128>>>(mask);
    oproj_gemm_kernel<<<dim3(MTOT/128, HID/128), 256, GEMM_SMEM>>>(out);
}

// round 4
// speedup vs baseline: 1.8027x; 1.7017x over previous
#include <cuda_runtime.h>
#include <cuda_fp16.h>
#include <mma.h>
#include <stdint.h>

using namespace nvcuda;

#define HID    1024
#define NHEADS 16
#define DK     64
#define BATCH  2
#define SEQ    2048
#define MTOT   (BATCH*SEQ)   // 4096
#define NKSTEP (HID/32)      // 32 k-steps of 32

// ----------------------------------------------------------------------------
// Scratch
// ----------------------------------------------------------------------------
__device__ __align__(256) __half g_Xhi[3][MTOT*HID];
__device__ __align__(256) __half g_Xlo[3][MTOT*HID];
__device__ __align__(256) __half g_Whi[4][HID*HID];
__device__ __align__(256) __half g_Wlo[4][HID*HID];
__device__ __align__(256) __half g_QKVhi[3][MTOT*HID];  // [b,h,s,d]
__device__ __align__(256) __half g_QKVlo[3][MTOT*HID];
__device__ __align__(256) __half g_AOhi[MTOT*HID];      // [b,s,h*d]
__device__ __align__(256) __half g_AOlo[MTOT*HID];
__device__ unsigned char g_mflag[BATCH*32*32];          // [b][q64][j64] any-mask flags

// ----------------------------------------------------------------------------
// PTX helpers
// ----------------------------------------------------------------------------
__device__ __forceinline__ void cpa(uint32_t s, const void* g) {
    asm volatile("cp.async.cg.shared.global [%0], [%1], 16;" :: "r"(s), "l"(g));
}
__device__ __forceinline__ void mma_f16(float* c, const uint32_t* a, const uint32_t* b) {
    asm volatile(
        "mma.sync.aligned.m16n8k16.row.col.f32.f16.f16.f32 "
        "{%0,%1,%2,%3}, {%4,%5,%6,%7}, {%8,%9}, {%0,%1,%2,%3};"
        : "+f"(c[0]), "+f"(c[1]), "+f"(c[2]), "+f"(c[3])
        : "r"(a[0]), "r"(a[1]), "r"(a[2]), "r"(a[3]), "r"(b[0]), "r"(b[1]));
}
__device__ __forceinline__ void ldsm_x4(uint32_t* r, uint32_t addr) {
    asm volatile("ldmatrix.sync.aligned.m8n8.x4.shared.b16 {%0,%1,%2,%3}, [%4];"
        : "=r"(r[0]), "=r"(r[1]), "=r"(r[2]), "=r"(r[3]) : "r"(addr));
}
__device__ __forceinline__ void ldsm_x4_t(uint32_t* r, uint32_t addr) {
    asm volatile("ldmatrix.sync.aligned.m8n8.x4.trans.shared.b16 {%0,%1,%2,%3}, [%4];"
        : "=r"(r[0]), "=r"(r[1]), "=r"(r[2]), "=r"(r[3]) : "r"(addr));
}
__device__ __forceinline__ uint32_t pk(float a, float b) {
    __half2 h = __floats2half2_rn(a, b);
    return *(uint32_t*)&h;
}
__device__ __forceinline__ uint32_t sm32(const void* p) {
    return (uint32_t)__cvta_generic_to_shared(p);
}

// ----------------------------------------------------------------------------
// fp32 -> (hi,lo) split, all 7 tensors in one launch
// ----------------------------------------------------------------------------
__global__ void __launch_bounds__(256) f2hl_all(
    const float* __restrict__ q, const float* __restrict__ k,
    const float* __restrict__ v, const float* __restrict__ wq,
    const float* __restrict__ wk, const float* __restrict__ wv,
    const float* __restrict__ wo)
{
    int sel = blockIdx.y;
    const float* src; __half* hi; __half* lo; int n;
    switch (sel) {
        case 0: src=q;  hi=g_Xhi[0]; lo=g_Xlo[0]; n=MTOT*HID; break;
        case 1: src=k;  hi=g_Xhi[1]; lo=g_Xlo[1]; n=MTOT*HID; break;
        case 2: src=v;  hi=g_Xhi[2]; lo=g_Xlo[2]; n=MTOT*HID; break;
        case 3: src=wq; hi=g_Whi[0]; lo=g_Wlo[0]; n=HID*HID;  break;
        case 4: src=wk; hi=g_Whi[1]; lo=g_Wlo[1]; n=HID*HID;  break;
        case 5: src=wv; hi=g_Whi[2]; lo=g_Wlo[2]; n=HID*HID;  break;
        default:src=wo; hi=g_Whi[3]; lo=g_Wlo[3]; n=HID*HID;  break;
    }
    int i = (blockIdx.x * 256 + threadIdx.x) * 4;
    if (i >= n) return;
    float4 x = *(const float4*)(src + i);
    __half h0 = __float2half_rn(x.x), h1 = __float2half_rn(x.y);
    __half h2 = __float2half_rn(x.z), h3 = __float2half_rn(x.w);
    ((__half2*)(hi + i))[0] = __halves2half2(h0, h1);
    ((__half2*)(hi + i))[1] = __halves2half2(h2, h3);
    ((__half2*)(lo + i))[0] = __halves2half2(__float2half_rn(x.x - __half2float(h0)),
                                             __float2half_rn(x.y - __half2float(h1)));
    ((__half2*)(lo + i))[1] = __halves2half2(__float2half_rn(x.z - __half2float(h2)),
                                             __float2half_rn(x.w - __half2float(h3)));
}

// ----------------------------------------------------------------------------
// Mask pre-pass: any-nonzero per (b, 64-row q tile, 64-col j tile)
// ----------------------------------------------------------------------------
__global__ void __launch_bounds__(128) mask_any_kernel(const unsigned char* __restrict__ mask) {
    int jt = blockIdx.x, qt = blockIdx.y, b = blockIdx.z;
    const unsigned char* base = mask + ((size_t)b*SEQ + qt*64) * SEQ + jt*64;
    int t = threadIdx.x;
    unsigned int acc = 0;
    #pragma unroll
    for (int i = 0; i < 2; i++) {
        int idx = t + i*128;
        int row = idx >> 2, col = (idx & 3) * 16;
        uint4 x = *(const uint4*)(base + (size_t)row * SEQ + col);
        acc |= x.x | x.y | x.z | x.w;
    }
    int any = __syncthreads_or(acc != 0u);
    if (t == 0) g_mflag[(b*32 + qt)*32 + jt] = any ? 1 : 0;
}

// ----------------------------------------------------------------------------
// GEMM smem layout (per stage, bytes): Ah 0, Al 10240, Bh 20480, Bl 30720
// stage size 40960; double buffered -> 81920 dynamic smem. k-step 32, pad 40.
// ----------------------------------------------------------------------------
#define G_STAGE 40960
#define G_SMEM  (2*G_STAGE)

__device__ __forceinline__ void gemm_stage_load(
    uint32_t sb, const __half* Agh, const __half* Agl,
    const __half* Bgh, const __half* Bgl, int m0, int n0, int k0, int t)
{
    #pragma unroll
    for (int i = 0; i < 2; i++) {
        int idx = t + i*256;
        int row = idx >> 2, col = (idx & 3) * 8;
        uint32_t so = (uint32_t)((row*40 + col) * 2);
        size_t ga = (size_t)(m0 + row) * HID + k0 + col;
        size_t gb = (size_t)(n0 + row) * HID + k0 + col;
        cpa(sb +         so, Agh + ga);
        cpa(sb + 10240 + so, Agl + ga);
        cpa(sb + 20480 + so, Bgh + gb);
        cpa(sb + 30720 + so, Bgl + gb);
    }
    asm volatile("cp.async.commit_group;");
}

#define GEMM_MAINLOOP(Agh_, Agl_, Bgh_, Bgl_)                                        \
    uint32_t smu = sm32(dsm);                                                        \
    gemm_stage_load(smu, Agh_, Agl_, Bgh_, Bgl_, m0, n0, 0, t);                      \
    for (int ks = 0; ks < NKSTEP; ks++) {                                            \
        if (ks + 1 < NKSTEP) {                                                       \
            gemm_stage_load(smu + ((ks+1)&1)*G_STAGE, Agh_, Agl_, Bgh_, Bgl_,        \
                            m0, n0, (ks+1)*32, t);                                   \
            asm volatile("cp.async.wait_group 1;");                                  \
        } else {                                                                     \
            asm volatile("cp.async.wait_group 0;");                                  \
        }                                                                            \
        __syncthreads();                                                             \
        {                                                                            \
            char* stg = dsm + (ks & 1) * G_STAGE;                                    \
            __half* Ah = (__half*)stg;                                               \
            __half* Al = (__half*)(stg + 10240);                                     \
            __half* Bh = (__half*)(stg + 20480);                                     \
            __half* Bl = (__half*)(stg + 30720);                                     \
            _Pragma("unroll")                                                        \
            for (int kk = 0; kk < 32; kk += 16) {                                    \
                wmma::fragment<wmma::matrix_a,16,16,16,__half,wmma::row_major> ah2[2], al2[2]; \
                _Pragma("unroll")                                                    \
                for (int mi = 0; mi < 2; mi++) {                                     \
                    wmma::load_matrix_sync(ah2[mi], Ah + (wm*32 + mi*16)*40 + kk, 40); \
                    wmma::load_matrix_sync(al2[mi], Al + (wm*32 + mi*16)*40 + kk, 40); \
                }                                                                    \
                _Pragma("unroll")                                                    \
                for (int j = 0; j < 4; j++) {                                        \
                    wmma::fragment<wmma::matrix_b,16,16,16,__half,wmma::col_major> bh2, bl2; \
                    wmma::load_matrix_sync(bh2, Bh + (wn*64 + j*16)*40 + kk, 40);    \
                    wmma::load_matrix_sync(bl2, Bl + (wn*64 + j*16)*40 + kk, 40);    \
                    _Pragma("unroll")                                                \
                    for (int mi = 0; mi < 2; mi++) {                                 \
                        wmma::mma_sync(acc[mi][j], ah2[mi], bh2, acc[mi][j]);        \
                        wmma::mma_sync(acc[mi][j], ah2[mi], bl2, acc[mi][j]);        \
                        wmma::mma_sync(acc[mi][j], al2[mi], bh2, acc[mi][j]);        \
                    }                                                                \
                }                                                                    \
            }                                                                        \
        }                                                                            \
        __syncthreads();                                                             \
    }

// ----------------------------------------------------------------------------
// QKV projection (3-term compensated), epilogue scatters to [b,h,s,d] hi/lo
// ----------------------------------------------------------------------------
__global__ void __launch_bounds__(256,2) proj_gemm_kernel() {
    extern __shared__ __align__(16) char dsm[];
    int z = blockIdx.z;
    const __half* Agh = g_Xhi[z]; const __half* Agl = g_Xlo[z];
    const __half* Bgh = g_Whi[z]; const __half* Bgl = g_Wlo[z];
    __half* Ohi = g_QKVhi[z];     __half* Olo = g_QKVlo[z];

    int m0 = blockIdx.x * 128, n0 = blockIdx.y * 128;
    int t = threadIdx.x, w = t >> 5;
    int wm = w & 3, wn = w >> 2;

    wmma::fragment<wmma::accumulator,16,16,16,float> acc[2][4];
    #pragma unroll
    for (int mi = 0; mi < 2; mi++)
        #pragma unroll
        for (int j = 0; j < 4; j++) wmma::fill_fragment(acc[mi][j], 0.0f);

    GEMM_MAINLOOP(Agh, Agl, Bgh, Bgl)

    float* Cs = (float*)dsm;  // 128x132 overlay = 67,584 B
    #pragma unroll
    for (int mi = 0; mi < 2; mi++)
        #pragma unroll
        for (int j = 0; j < 4; j++)
            wmma::store_matrix_sync(Cs + (wm*32 + mi*16)*132 + wn*64 + j*16,
                                    acc[mi][j], 132, wmma::mem_row_major);
    __syncthreads();

    for (int i = 0; i < 64; i++) {
        int idx = t + i*256; int r = idx >> 7; int c = idx & 127;
        float v0 = Cs[r*132 + c];
        int head = blockIdx.y*2 + (c >> 6); int d = c & 63;
        int rg = m0 + r; int b = rg >> 11; int s = rg & (SEQ-1);
        size_t o = (((size_t)b * NHEADS + head) * SEQ + s) * DK + d;
        __half hv = __float2half_rn(v0);
        Ohi[o] = hv;
        Olo[o] = __float2half_rn(v0 - __half2float(hv));
    }
}

// ----------------------------------------------------------------------------
// Output projection (3-term compensated), fp32 direct store
// ----------------------------------------------------------------------------
__global__ void __launch_bounds__(256,2) oproj_gemm_kernel(float* __restrict__ out) {
    extern __shared__ __align__(16) char dsm[];
    const __half* Agh = g_AOhi;   const __half* Agl = g_AOlo;
    const __half* Bgh = g_Whi[3]; const __half* Bgl = g_Wlo[3];

    int m0 = blockIdx.x * 128, n0 = blockIdx.y * 128;
    int t = threadIdx.x, w = t >> 5;
    int wm = w & 3, wn = w >> 2;

    wmma::fragment<wmma::accumulator,16,16,16,float> acc[2][4];
    #pragma unroll
    for (int mi = 0; mi < 2; mi++)
        #pragma unroll
        for (int j = 0; j < 4; j++) wmma::fill_fragment(acc[mi][j], 0.0f);

    GEMM_MAINLOOP(Agh, Agl, Bgh, Bgl)

    #pragma unroll
    for (int mi = 0; mi < 2; mi++)
        #pragma unroll
        for (int j = 0; j < 4; j++)
            wmma::store_matrix_sync(out + (size_t)(m0 + wm*32 + mi*16) * HID + n0 + wn*64 + j*16,
                                    acc[mi][j], HID, wmma::mem_row_major);
}

// ----------------------------------------------------------------------------
// Flash attention: ldmatrix fragments, register S/O, warp-local softmax,
// mask applied only when pre-pass flag set.
// ----------------------------------------------------------------------------
__global__ void __launch_bounds__(128,2) attn_kernel(const unsigned char* __restrict__ mask) {
    __shared__ __align__(16) __half Kh[64*72], Kl[64*72], Vh[64*72], Vl[64*72];
    __shared__ __align__(16) unsigned char Msk[64*64];

    int t = threadIdx.x, lane = t & 31, w = t >> 5;
    int gr = lane >> 2, qp = lane & 3;
    int qt = blockIdx.x, hd = blockIdx.y, b = blockIdx.z;
    int q0 = qt * 64;
    size_t base = ((size_t)b * NHEADS + hd) * SEQ;
    const __half* Qh_g = g_QKVhi[0] + (base + q0) * DK;
    const __half* Ql_g = g_QKVlo[0] + (base + q0) * DK;
    const __half* Kh_g = g_QKVhi[1] + base * DK;
    const __half* Kl_g = g_QKVlo[1] + base * DK;
    const __half* Vh_g = g_QKVhi[2] + base * DK;
    const __half* Vl_g = g_QKVlo[2] + base * DK;

    int r0 = w*16 + gr;
    int r1 = r0 + 8;

    // Q fragments with 0.125 scale folded (exact pow2)
    const __half2 sc = __float2half2_rn(0.125f);
    uint32_t qa[2][4][4];
    #pragma unroll
    for (int kc = 0; kc < 4; kc++) {
        int cb = kc*16 + qp*2;
        __half2 v;
        v = __hmul2(*(const __half2*)(Qh_g + r0*DK + cb),     sc); qa[0][kc][0] = *(uint32_t*)&v;
        v = __hmul2(*(const __half2*)(Qh_g + r1*DK + cb),     sc); qa[0][kc][1] = *(uint32_t*)&v;
        v = __hmul2(*(const __half2*)(Qh_g + r0*DK + cb + 8), sc); qa[0][kc][2] = *(uint32_t*)&v;
        v = __hmul2(*(const __half2*)(Qh_g + r1*DK + cb + 8), sc); qa[0][kc][3] = *(uint32_t*)&v;
        v = __hmul2(*(const __half2*)(Ql_g + r0*DK + cb),     sc); qa[1][kc][0] = *(uint32_t*)&v;
        v = __hmul2(*(const __half2*)(Ql_g + r1*DK + cb),     sc); qa[1][kc][1] = *(uint32_t*)&v;
        v = __hmul2(*(const __half2*)(Ql_g + r0*DK + cb + 8), sc); qa[1][kc][2] = *(uint32_t*)&v;
        v = __hmul2(*(const __half2*)(Ql_g + r1*DK + cb + 8), sc); qa[1][kc][3] = *(uint32_t*)&v;
    }

    float o[8][4];
    #pragma unroll
    for (int n = 0; n < 8; n++) { o[n][0]=0.f; o[n][1]=0.f; o[n][2]=0.f; o[n][3]=0.f; }
    float m0v = -1e30f, m1v = -1e30f, l0 = 0.f, l1 = 0.f;

    const unsigned char* flagrow = g_mflag + (b*32 + qt)*32;

    for (int j0 = 0, jt = 0; j0 < SEQ; j0 += 64, jt++) {
        int anym = flagrow[jt];

        // Cooperative smem fill: K, V hi/lo, all row-major [j][d] (no transpose)
        #pragma unroll
        for (int i = 0; i < 4; i++) {
            int idx = t + i*128; int row = idx >> 3; int col = (idx & 7) * 8;
            size_t g = (size_t)(j0 + row) * DK + col;
            *(uint4*)(Kh + row*72 + col) = *(const uint4*)(Kh_g + g);
            *(uint4*)(Kl + row*72 + col) = *(const uint4*)(Kl_g + g);
            *(uint4*)(Vh + row*72 + col) = *(const uint4*)(Vh_g + g);
            *(uint4*)(Vl + row*72 + col) = *(const uint4*)(Vl_g + g);
        }
        if (anym) {
            #pragma unroll
            for (int i = 0; i < 2; i++) {
                int idx = t + i*128; int rl = idx >> 2, cl = (idx & 3) * 16;
                *(uint4*)(Msk + rl*64 + cl) =
                    *(const uint4*)(mask + ((size_t)b*SEQ + q0 + rl) * SEQ + j0 + cl);
            }
        }
        __syncthreads();

        // S = (Q*sc) @ K^T, 3-term compensated; K fragments via ldmatrix.x4
        float s[8][4];
        #pragma unroll
        for (int n = 0; n < 8; n++) { s[n][0]=0.f; s[n][1]=0.f; s[n][2]=0.f; s[n][3]=0.f; }
        #pragma unroll
        for (int kc = 0; kc < 4; kc++) {
            #pragma unroll
            for (int np = 0; np < 4; np++) {
                int j = np*16 + (lane & 7) + ((lane >> 4) << 3);
                int d = kc*16 + ((lane >> 3) & 1) * 8;
                uint32_t kh4[4], kl4[4];
                ldsm_x4(kh4, sm32(Kh + j*72 + d));
                ldsm_x4(kl4, sm32(Kl + j*72 + d));
                mma_f16(s[2*np],   qa[0][kc], kh4);
                mma_f16(s[2*np],   qa[0][kc], kl4);
                mma_f16(s[2*np],   qa[1][kc], kh4);
                mma_f16(s[2*np+1], qa[0][kc], kh4+2);
                mma_f16(s[2*np+1], qa[0][kc], kl4+2);
                mma_f16(s[2*np+1], qa[1][kc], kh4+2);
            }
        }

        // Mask (only when flag set) + warp-local online softmax
        if (anym) {
            const unsigned char* mr0 = Msk + r0*64;
            const unsigned char* mr1 = Msk + r1*64;
            #pragma unroll
            for (int n = 0; n < 8; n++) {
                #pragma unroll
                for (int e = 0; e < 2; e++) {
                    int c = n*8 + qp*2 + e;
                    if (mr0[c]) s[n][e]   = -1e9f;
                    if (mr1[c]) s[n][2+e] = -1e9f;
                }
            }
        }
        float mx0 = -1e30f, mx1 = -1e30f;
        #pragma unroll
        for (int n = 0; n < 8; n++) {
            mx0 = fmaxf(mx0, fmaxf(s[n][0], s[n][1]));
            mx1 = fmaxf(mx1, fmaxf(s[n][2], s[n][3]));
        }
        mx0 = fmaxf(mx0, __shfl_xor_sync(0xffffffffu, mx0, 1));
        mx0 = fmaxf(mx0, __shfl_xor_sync(0xffffffffu, mx0, 2));
        mx1 = fmaxf(mx1, __shfl_xor_sync(0xffffffffu, mx1, 1));
        mx1 = fmaxf(mx1, __shfl_xor_sync(0xffffffffu, mx1, 2));
        float mn0 = fmaxf(m0v, mx0), mn1 = fmaxf(m1v, mx1);

        float sum0 = 0.f, sum1 = 0.f;
        uint32_t pa[4][4];
        #pragma unroll
        for (int n = 0; n < 8; n++) {
            float p0 = __expf(s[n][0] - mn0);
            float p1 = __expf(s[n][1] - mn0);
            float p2 = __expf(s[n][2] - mn1);
            float p3 = __expf(s[n][3] - mn1);
            sum0 += p0 + p1; sum1 += p2 + p3;
            int kc = n >> 1, h = (n & 1) * 2;
            pa[kc][h]     = pk(p0, p1);
            pa[kc][h + 1] = pk(p2, p3);
        }
        sum0 += __shfl_xor_sync(0xffffffffu, sum0, 1);
        sum0 += __shfl_xor_sync(0xffffffffu, sum0, 2);
        sum1 += __shfl_xor_sync(0xffffffffu, sum1, 1);
        sum1 += __shfl_xor_sync(0xffffffffu, sum1, 2);

        float ef0 = __expf(m0v - mn0), ef1 = __expf(m1v - mn1);
        l0 = l0*ef0 + sum0; l1 = l1*ef1 + sum1;
        m0v = mn0; m1v = mn1;
        #pragma unroll
        for (int n = 0; n < 8; n++) {
            o[n][0] *= ef0; o[n][1] *= ef0; o[n][2] *= ef1; o[n][3] *= ef1;
        }

        // O += P @ V ; V fragments via ldmatrix.x4.trans (row-major V)
        #pragma unroll
        for (int kc = 0; kc < 4; kc++) {
            #pragma unroll
            for (int dp = 0; dp < 4; dp++) {
                int j = kc*16 + (lane & 7) + (((lane >> 3) & 1) << 3);
                int d = dp*16 + ((lane >> 4) << 3);
                uint32_t vh4[4], vl4[4];
                ldsm_x4_t(vh4, sm32(Vh + j*72 + d));
                ldsm_x4_t(vl4, sm32(Vl + j*72 + d));
                mma_f16(o[2*dp],   pa[kc], vh4);
                mma_f16(o[2*dp],   pa[kc], vl4);
                mma_f16(o[2*dp+1], pa[kc], vh4+2);
                mma_f16(o[2*dp+1], pa[kc], vl4+2);
            }
        }
        __syncthreads();
    }

    // Epilogue: normalize, split hi/lo, write [b,s,h*64+d]
    float inv0 = 1.0f / l0, inv1 = 1.0f / l1;
    #pragma unroll
    for (int n = 0; n < 8; n++) {
        int col = n*8 + qp*2;
        float a0 = o[n][0]*inv0, a1 = o[n][1]*inv0;
        float b0 = o[n][2]*inv1, b1 = o[n][3]*inv1;
        __half h00 = __float2half_rn(a0), h01 = __float2half_rn(a1);
        __half h10 = __float2half_rn(b0), h11 = __float2half_rn(b1);
        size_t off0 = ((size_t)b*SEQ + q0 + r0) * HID + hd*DK + col;
        size_t off1 = ((size_t)b*SEQ + q0 + r1) * HID + hd*DK + col;
        *(__half2*)(g_AOhi + off0) = __halves2half2(h00, h01);
        *(__half2*)(g_AOhi + off1) = __halves2half2(h10, h11);
        *(__half2*)(g_AOlo + off0) = __halves2half2(
            __float2half_rn(a0 - __half2float(h00)), __float2half_rn(a1 - __half2float(h01)));
        *(__half2*)(g_AOlo + off1) = __halves2half2(
            __float2half_rn(b0 - __half2float(h10)), __float2half_rn(b1 - __half2float(h11)));
    }
}

// ----------------------------------------------------------------------------
// Launch
// ----------------------------------------------------------------------------
extern "C" void kernel_launch(void* const* d_in, const int* in_sizes, int n_in,
                              void* d_out, int out_size) {
    const float* q    = (const float*)d_in[0];
    const float* k    = (const float*)d_in[1];
    const float* v    = (const float*)d_in[2];
    const unsigned char* mask = (const unsigned char*)d_in[3];
    const float* Wq   = (const float*)d_in[4];
    const float* Wk   = (const float*)d_in[5];
    const float* Wv   = (const float*)d_in[6];
    const float* Wo   = (const float*)d_in[7];
    float* out = (float*)d_out;

    cudaFuncSetAttribute(proj_gemm_kernel,  cudaFuncAttributeMaxDynamicSharedMemorySize, G_SMEM);
    cudaFuncSetAttribute(oproj_gemm_kernel, cudaFuncAttributeMaxDynamicSharedMemorySize, G_SMEM);

    f2hl_all<<<dim3(MTOT*HID/(256*4), 7), 256>>>(q, k, v, Wq, Wk, Wv, Wo);
    mask_any_kernel<<<dim3(32, 32, BATCH), 128>>>(mask);
    proj_gemm_kernel<<<dim3(MTOT/128, HID/128, 3), 256, G_SMEM>>>();
    attn_kernel<<<dim3(SEQ/64, NHEADS, BATCH), 128>>>(mask);
    oproj_gemm_kernel<<<dim3(MTOT/128, HID/128), 256, G_SMEM>>>(out);
}

// round 8
// speedup vs baseline: 2.2068x; 1.2242x over previous
#include <cuda_runtime.h>
#include <cuda_fp16.h>
#include <mma.h>
#include <stdint.h>

using namespace nvcuda;

#define HID    1024
#define NHEADS 16
#define DK     64
#define BATCH  2
#define SEQ    2048
#define MTOT   (BATCH*SEQ)   // 4096
#define NKSTEP (HID/32)      // 32 k-steps of 32

// ----------------------------------------------------------------------------
// Scratch
// ----------------------------------------------------------------------------
__device__ __align__(256) __half g_Xhi[3][MTOT*HID];
__device__ __align__(256) __half g_Xlo[3][MTOT*HID];
__device__ __align__(256) __half g_Whi[4][HID*HID];
__device__ __align__(256) __half g_Wlo[4][HID*HID];
__device__ __align__(256) __half g_QKVhi[3][MTOT*HID];  // [b,h,s,d]
__device__ __align__(256) __half g_Qlo[MTOT*HID];       // lo only needed for Q
__device__ __align__(256) __half g_AOhi[MTOT*HID];      // [b,s,h*d]
__device__ __align__(256) __half g_AOlo[MTOT*HID];
__device__ unsigned char g_mflag[BATCH*32*32];          // [b][q64][j64] any-mask flags

// ----------------------------------------------------------------------------
// PTX helpers
// ----------------------------------------------------------------------------
__device__ __forceinline__ void cpa(uint32_t s, const void* g) {
    asm volatile("cp.async.cg.shared.global [%0], [%1], 16;" :: "r"(s), "l"(g));
}
__device__ __forceinline__ void mma_f16(float* c, const uint32_t* a, const uint32_t* b) {
    asm volatile(
        "mma.sync.aligned.m16n8k16.row.col.f32.f16.f16.f32 "
        "{%0,%1,%2,%3}, {%4,%5,%6,%7}, {%8,%9}, {%0,%1,%2,%3};"
        : "+f"(c[0]), "+f"(c[1]), "+f"(c[2]), "+f"(c[3])
        : "r"(a[0]), "r"(a[1]), "r"(a[2]), "r"(a[3]), "r"(b[0]), "r"(b[1]));
}
__device__ __forceinline__ void ldsm_x4(uint32_t* r, uint32_t addr) {
    asm volatile("ldmatrix.sync.aligned.m8n8.x4.shared.b16 {%0,%1,%2,%3}, [%4];"
        : "=r"(r[0]), "=r"(r[1]), "=r"(r[2]), "=r"(r[3]) : "r"(addr));
}
__device__ __forceinline__ void ldsm_x4_t(uint32_t* r, uint32_t addr) {
    asm volatile("ldmatrix.sync.aligned.m8n8.x4.trans.shared.b16 {%0,%1,%2,%3}, [%4];"
        : "=r"(r[0]), "=r"(r[1]), "=r"(r[2]), "=r"(r[3]) : "r"(addr));
}
__device__ __forceinline__ uint32_t pk(float a, float b) {
    __half2 h = __floats2half2_rn(a, b);
    return *(uint32_t*)&h;
}
__device__ __forceinline__ uint32_t sm32(const void* p) {
    return (uint32_t)__cvta_generic_to_shared(p);
}

// ----------------------------------------------------------------------------
// fp32 -> (hi,lo) split, all 7 tensors in one launch
// ----------------------------------------------------------------------------
__global__ void __launch_bounds__(256) f2hl_all(
    const float* __restrict__ q, const float* __restrict__ k,
    const float* __restrict__ v, const float* __restrict__ wq,
    const float* __restrict__ wk, const float* __restrict__ wv,
    const float* __restrict__ wo)
{
    int sel = blockIdx.y;
    const float* src; __half* hi; __half* lo; int n;
    switch (sel) {
        case 0: src=q;  hi=g_Xhi[0]; lo=g_Xlo[0]; n=MTOT*HID; break;
        case 1: src=k;  hi=g_Xhi[1]; lo=g_Xlo[1]; n=MTOT*HID; break;
        case 2: src=v;  hi=g_Xhi[2]; lo=g_Xlo[2]; n=MTOT*HID; break;
        case 3: src=wq; hi=g_Whi[0]; lo=g_Wlo[0]; n=HID*HID;  break;
        case 4: src=wk; hi=g_Whi[1]; lo=g_Wlo[1]; n=HID*HID;  break;
        case 5: src=wv; hi=g_Whi[2]; lo=g_Wlo[2]; n=HID*HID;  break;
        default:src=wo; hi=g_Whi[3]; lo=g_Wlo[3]; n=HID*HID;  break;
    }
    int i = (blockIdx.x * 256 + threadIdx.x) * 4;
    if (i >= n) return;
    float4 x = *(const float4*)(src + i);
    __half h0 = __float2half_rn(x.x), h1 = __float2half_rn(x.y);
    __half h2 = __float2half_rn(x.z), h3 = __float2half_rn(x.w);
    ((__half2*)(hi + i))[0] = __halves2half2(h0, h1);
    ((__half2*)(hi + i))[1] = __halves2half2(h2, h3);
    ((__half2*)(lo + i))[0] = __halves2half2(__float2half_rn(x.x - __half2float(h0)),
                                             __float2half_rn(x.y - __half2float(h1)));
    ((__half2*)(lo + i))[1] = __halves2half2(__float2half_rn(x.z - __half2float(h2)),
                                             __float2half_rn(x.w - __half2float(h3)));
}

// ----------------------------------------------------------------------------
// Mask pre-pass: any-nonzero per (b, 64-row q tile, 64-col j tile)
// ----------------------------------------------------------------------------
__global__ void __launch_bounds__(128) mask_any_kernel(const unsigned char* __restrict__ mask) {
    int jt = blockIdx.x, qt = blockIdx.y, b = blockIdx.z;
    const unsigned char* base = mask + ((size_t)b*SEQ + qt*64) * SEQ + jt*64;
    int t = threadIdx.x;
    unsigned int acc = 0;
    #pragma unroll
    for (int i = 0; i < 2; i++) {
        int idx = t + i*128;
        int row = idx >> 2, col = (idx & 3) * 16;
        uint4 x = *(const uint4*)(base + (size_t)row * SEQ + col);
        acc |= x.x | x.y | x.z | x.w;
    }
    int any = __syncthreads_or(acc != 0u);
    if (t == 0) g_mflag[(b*32 + qt)*32 + jt] = any ? 1 : 0;
}

// ----------------------------------------------------------------------------
// GEMM: 128x128 tile, 256 thr, k-step 32, cp.async double buffer (3-term)
// ----------------------------------------------------------------------------
#define G_STAGE 40960
#define G_SMEM  (2*G_STAGE)

__device__ __forceinline__ void gemm_stage_load(
    uint32_t sb, const __half* Agh, const __half* Agl,
    const __half* Bgh, const __half* Bgl, int m0, int n0, int k0, int t)
{
    #pragma unroll
    for (int i = 0; i < 2; i++) {
        int idx = t + i*256;
        int row = idx >> 2, col = (idx & 3) * 8;
        uint32_t so = (uint32_t)((row*40 + col) * 2);
        size_t ga = (size_t)(m0 + row) * HID + k0 + col;
        size_t gb = (size_t)(n0 + row) * HID + k0 + col;
        cpa(sb +         so, Agh + ga);
        cpa(sb + 10240 + so, Agl + ga);
        cpa(sb + 20480 + so, Bgh + gb);
        cpa(sb + 30720 + so, Bgl + gb);
    }
    asm volatile("cp.async.commit_group;");
}

#define GEMM_MAINLOOP(Agh_, Agl_, Bgh_, Bgl_)                                        \
    uint32_t smu = sm32(dsm);                                                        \
    gemm_stage_load(smu, Agh_, Agl_, Bgh_, Bgl_, m0, n0, 0, t);                      \
    for (int ks = 0; ks < NKSTEP; ks++) {                                            \
        if (ks + 1 < NKSTEP) {                                                       \
            gemm_stage_load(smu + ((ks+1)&1)*G_STAGE, Agh_, Agl_, Bgh_, Bgl_,        \
                            m0, n0, (ks+1)*32, t);                                   \
            asm volatile("cp.async.wait_group 1;");                                  \
        } else {                                                                     \
            asm volatile("cp.async.wait_group 0;");                                  \
        }                                                                            \
        __syncthreads();                                                             \
        {                                                                            \
            char* stg = dsm + (ks & 1) * G_STAGE;                                    \
            __half* Ah = (__half*)stg;                                               \
            __half* Al = (__half*)(stg + 10240);                                     \
            __half* Bh = (__half*)(stg + 20480);                                     \
            __half* Bl = (__half*)(stg + 30720);                                     \
            _Pragma("unroll")                                                        \
            for (int kk = 0; kk < 32; kk += 16) {                                    \
                wmma::fragment<wmma::matrix_a,16,16,16,__half,wmma::row_major> ah2[2], al2[2]; \
                _Pragma("unroll")                                                    \
                for (int mi = 0; mi < 2; mi++) {                                     \
                    wmma::load_matrix_sync(ah2[mi], Ah + (wm*32 + mi*16)*40 + kk, 40); \
                    wmma::load_matrix_sync(al2[mi], Al + (wm*32 + mi*16)*40 + kk, 40); \
                }                                                                    \
                _Pragma("unroll")                                                    \
                for (int j = 0; j < 4; j++) {                                        \
                    wmma::fragment<wmma::matrix_b,16,16,16,__half,wmma::col_major> bh2, bl2; \
                    wmma::load_matrix_sync(bh2, Bh + (wn*64 + j*16)*40 + kk, 40);    \
                    wmma::load_matrix_sync(bl2, Bl + (wn*64 + j*16)*40 + kk, 40);    \
                    _Pragma("unroll")                                                \
                    for (int mi = 0; mi < 2; mi++) {                                 \
                        wmma::mma_sync(acc[mi][j], ah2[mi], bh2, acc[mi][j]);        \
                        wmma::mma_sync(acc[mi][j], ah2[mi], bl2, acc[mi][j]);        \
                        wmma::mma_sync(acc[mi][j], al2[mi], bh2, acc[mi][j]);        \
                    }                                                                \
                }                                                                    \
            }                                                                        \
        }                                                                            \
        __syncthreads();                                                             \
    }

// ----------------------------------------------------------------------------
// QKV projection (3-term). Epilogue: Q writes hi+lo; K,V write hi only.
// ----------------------------------------------------------------------------
__global__ void __launch_bounds__(256,2) proj_gemm_kernel() {
    extern __shared__ __align__(16) char dsm[];
    int z = blockIdx.z;
    const __half* Agh = g_Xhi[z]; const __half* Agl = g_Xlo[z];
    const __half* Bgh = g_Whi[z]; const __half* Bgl = g_Wlo[z];
    __half* Ohi = g_QKVhi[z];

    int m0 = blockIdx.x * 128, n0 = blockIdx.y * 128;
    int t = threadIdx.x, w = t >> 5;
    int wm = w & 3, wn = w >> 2;

    wmma::fragment<wmma::accumulator,16,16,16,float> acc[2][4];
    #pragma unroll
    for (int mi = 0; mi < 2; mi++)
        #pragma unroll
        for (int j = 0; j < 4; j++) wmma::fill_fragment(acc[mi][j], 0.0f);

    GEMM_MAINLOOP(Agh, Agl, Bgh, Bgl)

    float* Cs = (float*)dsm;  // 128x132 overlay
    #pragma unroll
    for (int mi = 0; mi < 2; mi++)
        #pragma unroll
        for (int j = 0; j < 4; j++)
            wmma::store_matrix_sync(Cs + (wm*32 + mi*16)*132 + wn*64 + j*16,
                                    acc[mi][j], 132, wmma::mem_row_major);
    __syncthreads();

    for (int i = 0; i < 64; i++) {
        int idx = t + i*256; int r = idx >> 7; int c = idx & 127;
        float v0 = Cs[r*132 + c];
        int head = blockIdx.y*2 + (c >> 6); int d = c & 63;
        int rg = m0 + r; int b = rg >> 11; int s = rg & (SEQ-1);
        size_t o = (((size_t)b * NHEADS + head) * SEQ + s) * DK + d;
        __half hv = __float2half_rn(v0);
        Ohi[o] = hv;
        if (z == 0) g_Qlo[o] = __float2half_rn(v0 - __half2float(hv));
    }
}

// ----------------------------------------------------------------------------
// Output projection (3-term), fp32 direct store
// ----------------------------------------------------------------------------
__global__ void __launch_bounds__(256,2) oproj_gemm_kernel(float* __restrict__ out) {
    extern __shared__ __align__(16) char dsm[];
    const __half* Agh = g_AOhi;   const __half* Agl = g_AOlo;
    const __half* Bgh = g_Whi[3]; const __half* Bgl = g_Wlo[3];

    int m0 = blockIdx.x * 128, n0 = blockIdx.y * 128;
    int t = threadIdx.x, w = t >> 5;
    int wm = w & 3, wn = w >> 2;

    wmma::fragment<wmma::accumulator,16,16,16,float> acc[2][4];
    #pragma unroll
    for (int mi = 0; mi < 2; mi++)
        #pragma unroll
        for (int j = 0; j < 4; j++) wmma::fill_fragment(acc[mi][j], 0.0f);

    GEMM_MAINLOOP(Agh, Agl, Bgh, Bgl)

    #pragma unroll
    for (int mi = 0; mi < 2; mi++)
        #pragma unroll
        for (int j = 0; j < 4; j++)
            wmma::store_matrix_sync(out + (size_t)(m0 + wm*32 + mi*16) * HID + n0 + wn*64 + j*16,
                                    acc[mi][j], HID, wmma::mem_row_major);
}

// ----------------------------------------------------------------------------
// Flash attention: fp16 K/V (hi only), Q 2-term; cp.async double-buffered K/V
// ----------------------------------------------------------------------------
__global__ void __launch_bounds__(128,3) attn_kernel(const unsigned char* __restrict__ mask) {
    __shared__ __align__(16) __half KV[2][2][64*72];   // [stage][K=0/V=1]
    __shared__ __align__(16) unsigned char Msk[64*64];

    int t = threadIdx.x, lane = t & 31, w = t >> 5;
    int gr = lane >> 2, qp = lane & 3;
    int qt = blockIdx.x, hd = blockIdx.y, b = blockIdx.z;
    int q0 = qt * 64;
    size_t base = ((size_t)b * NHEADS + hd) * SEQ;
    const __half* Qh_g = g_QKVhi[0] + (base + q0) * DK;
    const __half* Ql_g = g_Qlo      + (base + q0) * DK;
    const __half* Kh_g = g_QKVhi[1] + base * DK;
    const __half* Vh_g = g_QKVhi[2] + base * DK;

    int r0 = w*16 + gr;
    int r1 = r0 + 8;

    // Q fragments (hi+lo), 0.125 scale folded (exact pow2)
    const __half2 sc = __float2half2_rn(0.125f);
    uint32_t qa[2][4][4];
    #pragma unroll
    for (int kc = 0; kc < 4; kc++) {
        int cb = kc*16 + qp*2;
        __half2 v;
        v = __hmul2(*(const __half2*)(Qh_g + r0*DK + cb),     sc); qa[0][kc][0] = *(uint32_t*)&v;
        v = __hmul2(*(const __half2*)(Qh_g + r1*DK + cb),     sc); qa[0][kc][1] = *(uint32_t*)&v;
        v = __hmul2(*(const __half2*)(Qh_g + r0*DK + cb + 8), sc); qa[0][kc][2] = *(uint32_t*)&v;
        v = __hmul2(*(const __half2*)(Qh_g + r1*DK + cb + 8), sc); qa[0][kc][3] = *(uint32_t*)&v;
        v = __hmul2(*(const __half2*)(Ql_g + r0*DK + cb),     sc); qa[1][kc][0] = *(uint32_t*)&v;
        v = __hmul2(*(const __half2*)(Ql_g + r1*DK + cb),     sc); qa[1][kc][1] = *(uint32_t*)&v;
        v = __hmul2(*(const __half2*)(Ql_g + r0*DK + cb + 8), sc); qa[1][kc][2] = *(uint32_t*)&v;
        v = __hmul2(*(const __half2*)(Ql_g + r1*DK + cb + 8), sc); qa[1][kc][3] = *(uint32_t*)&v;
    }

    float o[8][4];
    #pragma unroll
    for (int n = 0; n < 8; n++) { o[n][0]=0.f; o[n][1]=0.f; o[n][2]=0.f; o[n][3]=0.f; }
    float m0v = -1e30f, m1v = -1e30f, l0 = 0.f, l1 = 0.f;

    const unsigned char* flagrow = g_mflag + (b*32 + qt)*32;

    // stage loader: K & V hi tiles via cp.async
    auto load_stage = [&](int jt, int stg) {
        #pragma unroll
        for (int i = 0; i < 4; i++) {
            int idx = t + i*128; int row = idx >> 3; int col = (idx & 7) * 8;
            size_t g = (size_t)(jt*64 + row) * DK + col;
            cpa(sm32(&KV[stg][0][row*72 + col]), Kh_g + g);
            cpa(sm32(&KV[stg][1][row*72 + col]), Vh_g + g);
        }
        asm volatile("cp.async.commit_group;");
    };

    load_stage(0, 0);

    for (int jt = 0; jt < SEQ/64; jt++) {
        int stg = jt & 1;
        if (jt + 1 < SEQ/64) {
            load_stage(jt+1, stg ^ 1);
            asm volatile("cp.async.wait_group 1;");
        } else {
            asm volatile("cp.async.wait_group 0;");
        }
        __syncthreads();

        int anym = flagrow[jt];
        if (anym) {
            #pragma unroll
            for (int i = 0; i < 2; i++) {
                int idx = t + i*128; int rl = idx >> 2, cl = (idx & 3) * 16;
                *(uint4*)(Msk + rl*64 + cl) =
                    *(const uint4*)(mask + ((size_t)b*SEQ + q0 + rl) * SEQ + jt*64 + cl);
            }
            __syncthreads();
        }

        __half* Kh = KV[stg][0];
        __half* Vh = KV[stg][1];

        // S = Q@K^T (2-term: (Qhi+Qlo)·Khi)
        float s[8][4];
        #pragma unroll
        for (int n = 0; n < 8; n++) { s[n][0]=0.f; s[n][1]=0.f; s[n][2]=0.f; s[n][3]=0.f; }
        #pragma unroll
        for (int kc = 0; kc < 4; kc++) {
            #pragma unroll
            for (int np = 0; np < 4; np++) {
                int j = np*16 + (lane & 7) + ((lane >> 4) << 3);
                int d = kc*16 + ((lane >> 3) & 1) * 8;
                uint32_t kh4[4];
                ldsm_x4(kh4, sm32(Kh + j*72 + d));
                mma_f16(s[2*np],   qa[0][kc], kh4);
                mma_f16(s[2*np],   qa[1][kc], kh4);
                mma_f16(s[2*np+1], qa[0][kc], kh4+2);
                mma_f16(s[2*np+1], qa[1][kc], kh4+2);
            }
        }

        if (anym) {
            const unsigned char* mr0 = Msk + r0*64;
            const unsigned char* mr1 = Msk + r1*64;
            #pragma unroll
            for (int n = 0; n < 8; n++) {
                #pragma unroll
                for (int e = 0; e < 2; e++) {
                    int c = n*8 + qp*2 + e;
                    if (mr0[c]) s[n][e]   = -1e9f;
                    if (mr1[c]) s[n][2+e] = -1e9f;
                }
            }
        }
        float mx0 = -1e30f, mx1 = -1e30f;
        #pragma unroll
        for (int n = 0; n < 8; n++) {
            mx0 = fmaxf(mx0, fmaxf(s[n][0], s[n][1]));
            mx1 = fmaxf(mx1, fmaxf(s[n][2], s[n][3]));
        }
        mx0 = fmaxf(mx0, __shfl_xor_sync(0xffffffffu, mx0, 1));
        mx0 = fmaxf(mx0, __shfl_xor_sync(0xffffffffu, mx0, 2));
        mx1 = fmaxf(mx1, __shfl_xor_sync(0xffffffffu, mx1, 1));
        mx1 = fmaxf(mx1, __shfl_xor_sync(0xffffffffu, mx1, 2));
        float mn0 = fmaxf(m0v, mx0), mn1 = fmaxf(m1v, mx1);

        float sum0 = 0.f, sum1 = 0.f;
        uint32_t pa[4][4];
        #pragma unroll
        for (int n = 0; n < 8; n++) {
            float p0 = __expf(s[n][0] - mn0);
            float p1 = __expf(s[n][1] - mn0);
            float p2 = __expf(s[n][2] - mn1);
            float p3 = __expf(s[n][3] - mn1);
            sum0 += p0 + p1; sum1 += p2 + p3;
            int kc = n >> 1, h = (n & 1) * 2;
            pa[kc][h]     = pk(p0, p1);
            pa[kc][h + 1] = pk(p2, p3);
        }
        sum0 += __shfl_xor_sync(0xffffffffu, sum0, 1);
        sum0 += __shfl_xor_sync(0xffffffffu, sum0, 2);
        sum1 += __shfl_xor_sync(0xffffffffu, sum1, 1);
        sum1 += __shfl_xor_sync(0xffffffffu, sum1, 2);

        float ef0 = __expf(m0v - mn0), ef1 = __expf(m1v - mn1);
        l0 = l0*ef0 + sum0; l1 = l1*ef1 + sum1;
        m0v = mn0; m1v = mn1;
        #pragma unroll
        for (int n = 0; n < 8; n++) {
            o[n][0] *= ef0; o[n][1] *= ef0; o[n][2] *= ef1; o[n][3] *= ef1;
        }

        // O += P @ V (V hi only), V fragments via ldmatrix.x4.trans
        #pragma unroll
        for (int kc = 0; kc < 4; kc++) {
            #pragma unroll
            for (int dp = 0; dp < 4; dp++) {
                int j = kc*16 + (lane & 7) + (((lane >> 3) & 1) << 3);
                int d = dp*16 + ((lane >> 4) << 3);
                uint32_t vh4[4];
                ldsm_x4_t(vh4, sm32(Vh + j*72 + d));
                mma_f16(o[2*dp],   pa[kc], vh4);
                mma_f16(o[2*dp+1], pa[kc], vh4+2);
            }
        }
        __syncthreads();
    }

    // Epilogue: normalize, split hi/lo, write [b,s,h*64+d]
    float inv0 = 1.0f / l0, inv1 = 1.0f / l1;
    #pragma unroll
    for (int n = 0; n < 8; n++) {
        int col = n*8 + qp*2;
        float a0 = o[n][0]*inv0, a1 = o[n][1]*inv0;
        float b0 = o[n][2]*inv1, b1 = o[n][3]*inv1;
        __half h00 = __float2half_rn(a0), h01 = __float2half_rn(a1);
        __half h10 = __float2half_rn(b0), h11 = __float2half_rn(b1);
        size_t off0 = ((size_t)b*SEQ + q0 + r0) * HID + hd*DK + col;
        size_t off1 = ((size_t)b*SEQ + q0 + r1) * HID + hd*DK + col;
        *(__half2*)(g_AOhi + off0) = __halves2half2(h00, h01);
        *(__half2*)(g_AOhi + off1) = __halves2half2(h10, h11);
        *(__half2*)(g_AOlo + off0) = __halves2half2(
            __float2half_rn(a0 - __half2float(h00)), __float2half_rn(a1 - __half2float(h01)));
        *(__half2*)(g_AOlo + off1) = __halves2half2(
            __float2half_rn(b0 - __half2float(h10)), __float2half_rn(b1 - __half2float(h11)));
    }
}

// ----------------------------------------------------------------------------
// Launch
// ----------------------------------------------------------------------------
extern "C" void kernel_launch(void* const* d_in, const int* in_sizes, int n_in,
                              void* d_out, int out_size) {
    const float* q    = (const float*)d_in[0];
    const float* k    = (const float*)d_in[1];
    const float* v    = (const float*)d_in[2];
    const unsigned char* mask = (const unsigned char*)d_in[3];
    const float* Wq   = (const float*)d_in[4];
    const float* Wk   = (const float*)d_in[5];
    const float* Wv   = (const float*)d_in[6];
    const float* Wo   = (const float*)d_in[7];
    float* out = (float*)d_out;

    cudaFuncSetAttribute(proj_gemm_kernel,  cudaFuncAttributeMaxDynamicSharedMemorySize, G_SMEM);
    cudaFuncSetAttribute(oproj_gemm_kernel, cudaFuncAttributeMaxDynamicSharedMemorySize, G_SMEM);

    f2hl_all<<<dim3(MTOT*HID/(256*4), 7), 256>>>(q, k, v, Wq, Wk, Wv, Wo);
    mask_any_kernel<<<dim3(32, 32, BATCH), 128>>>(mask);
    proj_gemm_kernel<<<dim3(MTOT/128, HID/128, 3), 256, G_SMEM>>>();
    attn_kernel<<<dim3(SEQ/64, NHEADS, BATCH), 128>>>(mask);
    oproj_gemm_kernel<<<dim3(MTOT/128, HID/128), 256, G_SMEM>>>(out);
}

// round 9
// speedup vs baseline: 2.9475x; 1.3357x over previous
#include <cuda_runtime.h>
#include <cuda_fp16.h>
#include <mma.h>
#include <stdint.h>

using namespace nvcuda;

#define HID    1024
#define NHEADS 16
#define DK     64
#define BATCH  2
#define SEQ    2048
#define MTOT   (BATCH*SEQ)   // 4096
#define NKSTEP (HID/32)      // 32 k-steps of 32

// ----------------------------------------------------------------------------
// Scratch
// ----------------------------------------------------------------------------
__device__ __align__(256) __half g_Xhi[3][MTOT*HID];
__device__ __align__(256) __half g_Whi[4][HID*HID];
__device__ __align__(256) __half g_Wlo[4][HID*HID];
__device__ __align__(256) __half g_QKVhi[3][MTOT*HID];  // [b,h,s,d]
__device__ __align__(256) __half g_AOhi[MTOT*HID];      // [b,s,h*d]
__device__ unsigned char g_mflag[BATCH*32*32];          // [b][q64][j64] any-mask flags

// ----------------------------------------------------------------------------
// PTX helpers
// ----------------------------------------------------------------------------
__device__ __forceinline__ void cpa(uint32_t s, const void* g) {
    asm volatile("cp.async.cg.shared.global [%0], [%1], 16;" :: "r"(s), "l"(g));
}
__device__ __forceinline__ void mma_f16(float* c, const uint32_t* a, const uint32_t* b) {
    asm volatile(
        "mma.sync.aligned.m16n8k16.row.col.f32.f16.f16.f32 "
        "{%0,%1,%2,%3}, {%4,%5,%6,%7}, {%8,%9}, {%0,%1,%2,%3};"
        : "+f"(c[0]), "+f"(c[1]), "+f"(c[2]), "+f"(c[3])
        : "r"(a[0]), "r"(a[1]), "r"(a[2]), "r"(a[3]), "r"(b[0]), "r"(b[1]));
}
__device__ __forceinline__ void ldsm_x4(uint32_t* r, uint32_t addr) {
    asm volatile("ldmatrix.sync.aligned.m8n8.x4.shared.b16 {%0,%1,%2,%3}, [%4];"
        : "=r"(r[0]), "=r"(r[1]), "=r"(r[2]), "=r"(r[3]) : "r"(addr));
}
__device__ __forceinline__ void ldsm_x4_t(uint32_t* r, uint32_t addr) {
    asm volatile("ldmatrix.sync.aligned.m8n8.x4.trans.shared.b16 {%0,%1,%2,%3}, [%4];"
        : "=r"(r[0]), "=r"(r[1]), "=r"(r[2]), "=r"(r[3]) : "r"(addr));
}
__device__ __forceinline__ uint32_t pk(float a, float b) {
    __half2 h = __floats2half2_rn(a, b);
    return *(uint32_t*)&h;
}
__device__ __forceinline__ uint32_t sm32(const void* p) {
    return (uint32_t)__cvta_generic_to_shared(p);
}

// ----------------------------------------------------------------------------
// fp32 -> fp16 split. Activations: hi only. Weights: hi + lo.
// ----------------------------------------------------------------------------
__global__ void __launch_bounds__(256) f2hl_all(
    const float* __restrict__ q, const float* __restrict__ k,
    const float* __restrict__ v, const float* __restrict__ wq,
    const float* __restrict__ wk, const float* __restrict__ wv,
    const float* __restrict__ wo)
{
    int sel = blockIdx.y;
    const float* src; __half* hi; __half* lo = 0; int n;
    switch (sel) {
        case 0: src=q;  hi=g_Xhi[0]; n=MTOT*HID; break;
        case 1: src=k;  hi=g_Xhi[1]; n=MTOT*HID; break;
        case 2: src=v;  hi=g_Xhi[2]; n=MTOT*HID; break;
        case 3: src=wq; hi=g_Whi[0]; lo=g_Wlo[0]; n=HID*HID; break;
        case 4: src=wk; hi=g_Whi[1]; lo=g_Wlo[1]; n=HID*HID; break;
        case 5: src=wv; hi=g_Whi[2]; lo=g_Wlo[2]; n=HID*HID; break;
        default:src=wo; hi=g_Whi[3]; lo=g_Wlo[3]; n=HID*HID; break;
    }
    int i = (blockIdx.x * 256 + threadIdx.x) * 4;
    if (i >= n) return;
    float4 x = *(const float4*)(src + i);
    __half h0 = __float2half_rn(x.x), h1 = __float2half_rn(x.y);
    __half h2 = __float2half_rn(x.z), h3 = __float2half_rn(x.w);
    ((__half2*)(hi + i))[0] = __halves2half2(h0, h1);
    ((__half2*)(hi + i))[1] = __halves2half2(h2, h3);
    if (lo) {
        ((__half2*)(lo + i))[0] = __halves2half2(__float2half_rn(x.x - __half2float(h0)),
                                                 __float2half_rn(x.y - __half2float(h1)));
        ((__half2*)(lo + i))[1] = __halves2half2(__float2half_rn(x.z - __half2float(h2)),
                                                 __float2half_rn(x.w - __half2float(h3)));
    }
}

// ----------------------------------------------------------------------------
// Mask pre-pass: any-nonzero per (b, 64-row q tile, 64-col j tile)
// ----------------------------------------------------------------------------
__global__ void __launch_bounds__(128) mask_any_kernel(const unsigned char* __restrict__ mask) {
    int jt = blockIdx.x, qt = blockIdx.y, b = blockIdx.z;
    const unsigned char* base = mask + ((size_t)b*SEQ + qt*64) * SEQ + jt*64;
    int t = threadIdx.x;
    unsigned int acc = 0;
    #pragma unroll
    for (int i = 0; i < 2; i++) {
        int idx = t + i*128;
        int row = idx >> 2, col = (idx & 3) * 16;
        uint4 x = *(const uint4*)(base + (size_t)row * SEQ + col);
        acc |= x.x | x.y | x.z | x.w;
    }
    int any = __syncthreads_or(acc != 0u);
    if (t == 0) g_mflag[(b*32 + qt)*32 + jt] = any ? 1 : 0;
}

// ----------------------------------------------------------------------------
// GEMM: 128x128 tile, 256 thr, k-step 32, 2-term (Ahi*Whi + Ahi*Wlo),
// 3-stage cp.async ring, ONE sync per k-step.
// Stage layout (bytes): Ah 0, Bh 10240, Bl 20480; stage = 30720.
// ----------------------------------------------------------------------------
#define G_STAGE 30720
#define G_NSTG  3
#define G_SMEM  (G_NSTG*G_STAGE)   // 92,160

__device__ __forceinline__ void gemm_stage_load(
    uint32_t sb, const __half* Agh, const __half* Bgh, const __half* Bgl,
    int m0, int n0, int k0, int t)
{
    #pragma unroll
    for (int i = 0; i < 2; i++) {
        int idx = t + i*256;
        int row = idx >> 2, col = (idx & 3) * 8;
        uint32_t so = (uint32_t)((row*40 + col) * 2);
        size_t ga = (size_t)(m0 + row) * HID + k0 + col;
        size_t gb = (size_t)(n0 + row) * HID + k0 + col;
        cpa(sb +         so, Agh + ga);
        cpa(sb + 10240 + so, Bgh + gb);
        cpa(sb + 20480 + so, Bgl + gb);
    }
    asm volatile("cp.async.commit_group;");
}

#define GEMM_MAINLOOP(Agh_, Bgh_, Bgl_)                                              \
    uint32_t smu = sm32(dsm);                                                        \
    gemm_stage_load(smu,           Agh_, Bgh_, Bgl_, m0, n0, 0,  t);                 \
    gemm_stage_load(smu + G_STAGE, Agh_, Bgh_, Bgl_, m0, n0, 32, t);                 \
    for (int ks = 0; ks < NKSTEP; ks++) {                                            \
        if (ks + 1 < NKSTEP) asm volatile("cp.async.wait_group 1;");                 \
        else                 asm volatile("cp.async.wait_group 0;");                 \
        __syncthreads();                                                             \
        if (ks + 2 < NKSTEP)                                                         \
            gemm_stage_load(smu + ((ks+2)%G_NSTG)*G_STAGE, Agh_, Bgh_, Bgl_,         \
                            m0, n0, (ks+2)*32, t);                                   \
        {                                                                            \
            char* stg = dsm + (ks % G_NSTG) * G_STAGE;                               \
            __half* Ah = (__half*)stg;                                               \
            __half* Bh = (__half*)(stg + 10240);                                     \
            __half* Bl = (__half*)(stg + 20480);                                     \
            _Pragma("unroll")                                                        \
            for (int kk = 0; kk < 32; kk += 16) {                                    \
                wmma::fragment<wmma::matrix_a,16,16,16,__half,wmma::row_major> ah2[2]; \
                _Pragma("unroll")                                                    \
                for (int mi = 0; mi < 2; mi++)                                       \
                    wmma::load_matrix_sync(ah2[mi], Ah + (wm*32 + mi*16)*40 + kk, 40); \
                _Pragma("unroll")                                                    \
                for (int j = 0; j < 4; j++) {                                        \
                    wmma::fragment<wmma::matrix_b,16,16,16,__half,wmma::col_major> bh2, bl2; \
                    wmma::load_matrix_sync(bh2, Bh + (wn*64 + j*16)*40 + kk, 40);    \
                    wmma::load_matrix_sync(bl2, Bl + (wn*64 + j*16)*40 + kk, 40);    \
                    _Pragma("unroll")                                                \
                    for (int mi = 0; mi < 2; mi++) {                                 \
                        wmma::mma_sync(acc[mi][j], ah2[mi], bh2, acc[mi][j]);        \
                        wmma::mma_sync(acc[mi][j], ah2[mi], bl2, acc[mi][j]);        \
                    }                                                                \
                }                                                                    \
            }                                                                        \
        }                                                                            \
    }

// ----------------------------------------------------------------------------
// QKV projection (2-term). Epilogue writes hi to [b,h,s,d].
// ----------------------------------------------------------------------------
__global__ void __launch_bounds__(256,2) proj_gemm_kernel() {
    extern __shared__ __align__(16) char dsm[];
    int z = blockIdx.z;
    const __half* Agh = g_Xhi[z];
    const __half* Bgh = g_Whi[z]; const __half* Bgl = g_Wlo[z];
    __half* Ohi = g_QKVhi[z];

    int m0 = blockIdx.x * 128, n0 = blockIdx.y * 128;
    int t = threadIdx.x, w = t >> 5;
    int wm = w & 3, wn = w >> 2;

    wmma::fragment<wmma::accumulator,16,16,16,float> acc[2][4];
    #pragma unroll
    for (int mi = 0; mi < 2; mi++)
        #pragma unroll
        for (int j = 0; j < 4; j++) wmma::fill_fragment(acc[mi][j], 0.0f);

    GEMM_MAINLOOP(Agh, Bgh, Bgl)
    __syncthreads();   // protect stage smem before Cs overlay

    float* Cs = (float*)dsm;  // 128x132 overlay = 67,584 B
    #pragma unroll
    for (int mi = 0; mi < 2; mi++)
        #pragma unroll
        for (int j = 0; j < 4; j++)
            wmma::store_matrix_sync(Cs + (wm*32 + mi*16)*132 + wn*64 + j*16,
                                    acc[mi][j], 132, wmma::mem_row_major);
    __syncthreads();

    for (int i = 0; i < 64; i++) {
        int idx = t + i*256; int r = idx >> 7; int c = idx & 127;
        float v0 = Cs[r*132 + c];
        int head = blockIdx.y*2 + (c >> 6); int d = c & 63;
        int rg = m0 + r; int b = rg >> 11; int s = rg & (SEQ-1);
        size_t o = (((size_t)b * NHEADS + head) * SEQ + s) * DK + d;
        Ohi[o] = __float2half_rn(v0);
    }
}

// ----------------------------------------------------------------------------
// Output projection (2-term), fp32 direct store
// ----------------------------------------------------------------------------
__global__ void __launch_bounds__(256,2) oproj_gemm_kernel(float* __restrict__ out) {
    extern __shared__ __align__(16) char dsm[];
    const __half* Agh = g_AOhi;
    const __half* Bgh = g_Whi[3]; const __half* Bgl = g_Wlo[3];

    int m0 = blockIdx.x * 128, n0 = blockIdx.y * 128;
    int t = threadIdx.x, w = t >> 5;
    int wm = w & 3, wn = w >> 2;

    wmma::fragment<wmma::accumulator,16,16,16,float> acc[2][4];
    #pragma unroll
    for (int mi = 0; mi < 2; mi++)
        #pragma unroll
        for (int j = 0; j < 4; j++) wmma::fill_fragment(acc[mi][j], 0.0f);

    GEMM_MAINLOOP(Agh, Bgh, Bgl)

    #pragma unroll
    for (int mi = 0; mi < 2; mi++)
        #pragma unroll
        for (int j = 0; j < 4; j++)
            wmma::store_matrix_sync(out + (size_t)(m0 + wm*32 + mi*16) * HID + n0 + wn*64 + j*16,
                                    acc[mi][j], HID, wmma::mem_row_major);
}

// ----------------------------------------------------------------------------
// Flash attention: all-fp16 operands, cp.async double-buffered K/V
// ----------------------------------------------------------------------------
__global__ void __launch_bounds__(128,3) attn_kernel(const unsigned char* __restrict__ mask) {
    __shared__ __align__(16) __half KV[2][2][64*72];   // [stage][K=0/V=1]
    __shared__ __align__(16) unsigned char Msk[64*64];

    int t = threadIdx.x, lane = t & 31, w = t >> 5;
    int gr = lane >> 2, qp = lane & 3;
    int qt = blockIdx.x, hd = blockIdx.y, b = blockIdx.z;
    int q0 = qt * 64;
    size_t base = ((size_t)b * NHEADS + hd) * SEQ;
    const __half* Qh_g = g_QKVhi[0] + (base + q0) * DK;
    const __half* Kh_g = g_QKVhi[1] + base * DK;
    const __half* Vh_g = g_QKVhi[2] + base * DK;

    int r0 = w*16 + gr;
    int r1 = r0 + 8;

    // Q fragments (hi only), 0.125 scale folded (exact pow2)
    const __half2 sc = __float2half2_rn(0.125f);
    uint32_t qa[4][4];
    #pragma unroll
    for (int kc = 0; kc < 4; kc++) {
        int cb = kc*16 + qp*2;
        __half2 v;
        v = __hmul2(*(const __half2*)(Qh_g + r0*DK + cb),     sc); qa[kc][0] = *(uint32_t*)&v;
        v = __hmul2(*(const __half2*)(Qh_g + r1*DK + cb),     sc); qa[kc][1] = *(uint32_t*)&v;
        v = __hmul2(*(const __half2*)(Qh_g + r0*DK + cb + 8), sc); qa[kc][2] = *(uint32_t*)&v;
        v = __hmul2(*(const __half2*)(Qh_g + r1*DK + cb + 8), sc); qa[kc][3] = *(uint32_t*)&v;
    }

    float o[8][4];
    #pragma unroll
    for (int n = 0; n < 8; n++) { o[n][0]=0.f; o[n][1]=0.f; o[n][2]=0.f; o[n][3]=0.f; }
    float m0v = -1e30f, m1v = -1e30f, l0 = 0.f, l1 = 0.f;

    const unsigned char* flagrow = g_mflag + (b*32 + qt)*32;

    auto load_stage = [&](int jt, int stg) {
        #pragma unroll
        for (int i = 0; i < 4; i++) {
            int idx = t + i*128; int row = idx >> 3; int col = (idx & 7) * 8;
            size_t g = (size_t)(jt*64 + row) * DK + col;
            cpa(sm32(&KV[stg][0][row*72 + col]), Kh_g + g);
            cpa(sm32(&KV[stg][1][row*72 + col]), Vh_g + g);
        }
        asm volatile("cp.async.commit_group;");
    };

    load_stage(0, 0);

    for (int jt = 0; jt < SEQ/64; jt++) {
        int stg = jt & 1;
        if (jt + 1 < SEQ/64) {
            load_stage(jt+1, stg ^ 1);
            asm volatile("cp.async.wait_group 1;");
        } else {
            asm volatile("cp.async.wait_group 0;");
        }
        __syncthreads();

        int anym = flagrow[jt];
        if (anym) {
            #pragma unroll
            for (int i = 0; i < 2; i++) {
                int idx = t + i*128; int rl = idx >> 2, cl = (idx & 3) * 16;
                *(uint4*)(Msk + rl*64 + cl) =
                    *(const uint4*)(mask + ((size_t)b*SEQ + q0 + rl) * SEQ + jt*64 + cl);
            }
            __syncthreads();
        }

        __half* Kh = KV[stg][0];
        __half* Vh = KV[stg][1];

        // S = Q@K^T (plain fp16)
        float s[8][4];
        #pragma unroll
        for (int n = 0; n < 8; n++) { s[n][0]=0.f; s[n][1]=0.f; s[n][2]=0.f; s[n][3]=0.f; }
        #pragma unroll
        for (int kc = 0; kc < 4; kc++) {
            #pragma unroll
            for (int np = 0; np < 4; np++) {
                int j = np*16 + (lane & 7) + ((lane >> 4) << 3);
                int d = kc*16 + ((lane >> 3) & 1) * 8;
                uint32_t kh4[4];
                ldsm_x4(kh4, sm32(Kh + j*72 + d));
                mma_f16(s[2*np],   qa[kc], kh4);
                mma_f16(s[2*np+1], qa[kc], kh4+2);
            }
        }

        if (anym) {
            const unsigned char* mr0 = Msk + r0*64;
            const unsigned char* mr1 = Msk + r1*64;
            #pragma unroll
            for (int n = 0; n < 8; n++) {
                #pragma unroll
                for (int e = 0; e < 2; e++) {
                    int c = n*8 + qp*2 + e;
                    if (mr0[c]) s[n][e]   = -1e9f;
                    if (mr1[c]) s[n][2+e] = -1e9f;
                }
            }
        }
        float mx0 = -1e30f, mx1 = -1e30f;
        #pragma unroll
        for (int n = 0; n < 8; n++) {
            mx0 = fmaxf(mx0, fmaxf(s[n][0], s[n][1]));
            mx1 = fmaxf(mx1, fmaxf(s[n][2], s[n][3]));
        }
        mx0 = fmaxf(mx0, __shfl_xor_sync(0xffffffffu, mx0, 1));
        mx0 = fmaxf(mx0, __shfl_xor_sync(0xffffffffu, mx0, 2));
        mx1 = fmaxf(mx1, __shfl_xor_sync(0xffffffffu, mx1, 1));
        mx1 = fmaxf(mx1, __shfl_xor_sync(0xffffffffu, mx1, 2));
        float mn0 = fmaxf(m0v, mx0), mn1 = fmaxf(m1v, mx1);

        float sum0 = 0.f, sum1 = 0.f;
        uint32_t pa[4][4];
        #pragma unroll
        for (int n = 0; n < 8; n++) {
            float p0 = __expf(s[n][0] - mn0);
            float p1 = __expf(s[n][1] - mn0);
            float p2 = __expf(s[n][2] - mn1);
            float p3 = __expf(s[n][3] - mn1);
            sum0 += p0 + p1; sum1 += p2 + p3;
            int kc = n >> 1, h = (n & 1) * 2;
            pa[kc][h]     = pk(p0, p1);
            pa[kc][h + 1] = pk(p2, p3);
        }
        sum0 += __shfl_xor_sync(0xffffffffu, sum0, 1);
        sum0 += __shfl_xor_sync(0xffffffffu, sum0, 2);
        sum1 += __shfl_xor_sync(0xffffffffu, sum1, 1);
        sum1 += __shfl_xor_sync(0xffffffffu, sum1, 2);

        float ef0 = __expf(m0v - mn0), ef1 = __expf(m1v - mn1);
        l0 = l0*ef0 + sum0; l1 = l1*ef1 + sum1;
        m0v = mn0; m1v = mn1;
        #pragma unroll
        for (int n = 0; n < 8; n++) {
            o[n][0] *= ef0; o[n][1] *= ef0; o[n][2] *= ef1; o[n][3] *= ef1;
        }

        // O += P @ V, V fragments via ldmatrix.x4.trans
        #pragma unroll
        for (int kc = 0; kc < 4; kc++) {
            #pragma unroll
            for (int dp = 0; dp < 4; dp++) {
                int j = kc*16 + (lane & 7) + (((lane >> 3) & 1) << 3);
                int d = dp*16 + ((lane >> 4) << 3);
                uint32_t vh4[4];
                ldsm_x4_t(vh4, sm32(Vh + j*72 + d));
                mma_f16(o[2*dp],   pa[kc], vh4);
                mma_f16(o[2*dp+1], pa[kc], vh4+2);
            }
        }
        __syncthreads();
    }

    // Epilogue: normalize, write hi to [b,s,h*64+d]
    float inv0 = 1.0f / l0, inv1 = 1.0f / l1;
    #pragma unroll
    for (int n = 0; n < 8; n++) {
        int col = n*8 + qp*2;
        float a0 = o[n][0]*inv0, a1 = o[n][1]*inv0;
        float b0 = o[n][2]*inv1, b1 = o[n][3]*inv1;
        size_t off0 = ((size_t)b*SEQ + q0 + r0) * HID + hd*DK + col;
        size_t off1 = ((size_t)b*SEQ + q0 + r1) * HID + hd*DK + col;
        *(__half2*)(g_AOhi + off0) = __floats2half2_rn(a0, a1);
        *(__half2*)(g_AOhi + off1) = __floats2half2_rn(b0, b1);
    }
}

// ----------------------------------------------------------------------------
// Launch
// ----------------------------------------------------------------------------
extern "C" void kernel_launch(void* const* d_in, const int* in_sizes, int n_in,
                              void* d_out, int out_size) {
    const float* q    = (const float*)d_in[0];
    const float* k    = (const float*)d_in[1];
    const float* v    = (const float*)d_in[2];
    const unsigned char* mask = (const unsigned char*)d_in[3];
    const float* Wq   = (const float*)d_in[4];
    const float* Wk   = (const float*)d_in[5];
    const float* Wv   = (const float*)d_in[6];
    const float* Wo   = (const float*)d_in[7];
    float* out = (float*)d_out;

    cudaFuncSetAttribute(proj_gemm_kernel,  cudaFuncAttributeMaxDynamicSharedMemorySize, G_SMEM);
    cudaFuncSetAttribute(oproj_gemm_kernel, cudaFuncAttributeMaxDynamicSharedMemorySize, G_SMEM);

    f2hl_all<<<dim3(MTOT*HID/(256*4), 7), 256>>>(q, k, v, Wq, Wk, Wv, Wo);
    mask_any_kernel<<<dim3(32, 32, BATCH), 128>>>(mask);
    proj_gemm_kernel<<<dim3(MTOT/128, HID/128, 3), 256, G_SMEM>>>();
    attn_kernel<<<dim3(SEQ/64, NHEADS, BATCH), 128>>>(mask);
    oproj_gemm_kernel<<<dim3(MTOT/128, HID/128), 256, G_SMEM>>>(out);
}

// round 12
// speedup vs baseline: 3.5094x; 1.1906x over previous
#include <cuda_runtime.h>
#include <cuda_fp16.h>
#include <mma.h>
#include <stdint.h>

using namespace nvcuda;

#define HID    1024
#define NHEADS 16
#define DK     64
#define BATCH  2
#define SEQ    2048
#define MTOT   (BATCH*SEQ)   // 4096
#define NKSTEP (HID/32)      // 32 k-steps of 32

// ----------------------------------------------------------------------------
// Scratch
// ----------------------------------------------------------------------------
__device__ __align__(256) __half g_Xhi[3][MTOT*HID];
__device__ __align__(256) __half g_Whi[4][HID*HID];
__device__ __align__(256) __half g_Wlo[4][HID*HID];   // only [2],[3] used now
__device__ __align__(256) __half g_QKVhi[3][MTOT*HID];  // [b,h,s,d]
__device__ __align__(256) __half g_AOhi[MTOT*HID];      // [b,s,h*d]
__device__ unsigned char g_mflag[BATCH*32*32];          // [b][q64][j64] any-mask flags

// ----------------------------------------------------------------------------
// PTX helpers
// ----------------------------------------------------------------------------
__device__ __forceinline__ void cpa(uint32_t s, const void* g) {
    asm volatile("cp.async.cg.shared.global [%0], [%1], 16;" :: "r"(s), "l"(g));
}
__device__ __forceinline__ void mma_f16(float* c, const uint32_t* a, const uint32_t* b) {
    asm volatile(
        "mma.sync.aligned.m16n8k16.row.col.f32.f16.f16.f32 "
        "{%0,%1,%2,%3}, {%4,%5,%6,%7}, {%8,%9}, {%0,%1,%2,%3};"
        : "+f"(c[0]), "+f"(c[1]), "+f"(c[2]), "+f"(c[3])
        : "r"(a[0]), "r"(a[1]), "r"(a[2]), "r"(a[3]), "r"(b[0]), "r"(b[1]));
}
__device__ __forceinline__ void ldsm_x4(uint32_t* r, uint32_t addr) {
    asm volatile("ldmatrix.sync.aligned.m8n8.x4.shared.b16 {%0,%1,%2,%3}, [%4];"
        : "=r"(r[0]), "=r"(r[1]), "=r"(r[2]), "=r"(r[3]) : "r"(addr));
}
__device__ __forceinline__ void ldsm_x4_t(uint32_t* r, uint32_t addr) {
    asm volatile("ldmatrix.sync.aligned.m8n8.x4.trans.shared.b16 {%0,%1,%2,%3}, [%4];"
        : "=r"(r[0]), "=r"(r[1]), "=r"(r[2]), "=r"(r[3]) : "r"(addr));
}
__device__ __forceinline__ uint32_t ex2h2(float a, float b) {
    __half2 h = __floats2half2_rn(a, b);
    uint32_t r = *(uint32_t*)&h, e;
    asm("ex2.approx.f16x2 %0, %1;" : "=r"(e) : "r"(r));
    return e;
}
__device__ __forceinline__ uint32_t sm32(const void* p) {
    return (uint32_t)__cvta_generic_to_shared(p);
}

// ----------------------------------------------------------------------------
// fp32 -> fp16. Activations + Wq,Wk: hi only. Wv,Wo: hi + lo.
// ----------------------------------------------------------------------------
__global__ void __launch_bounds__(256) f2hl_all(
    const float* __restrict__ q, const float* __restrict__ k,
    const float* __restrict__ v, const float* __restrict__ wq,
    const float* __restrict__ wk, const float* __restrict__ wv,
    const float* __restrict__ wo)
{
    int sel = blockIdx.y;
    const float* src; __half* hi; __half* lo = 0; int n;
    switch (sel) {
        case 0: src=q;  hi=g_Xhi[0]; n=MTOT*HID; break;
        case 1: src=k;  hi=g_Xhi[1]; n=MTOT*HID; break;
        case 2: src=v;  hi=g_Xhi[2]; n=MTOT*HID; break;
        case 3: src=wq; hi=g_Whi[0]; n=HID*HID; break;
        case 4: src=wk; hi=g_Whi[1]; n=HID*HID; break;
        case 5: src=wv; hi=g_Whi[2]; lo=g_Wlo[2]; n=HID*HID; break;
        default:src=wo; hi=g_Whi[3]; lo=g_Wlo[3]; n=HID*HID; break;
    }
    int i = (blockIdx.x * 256 + threadIdx.x) * 4;
    if (i >= n) return;
    float4 x = *(const float4*)(src + i);
    __half h0 = __float2half_rn(x.x), h1 = __float2half_rn(x.y);
    __half h2 = __float2half_rn(x.z), h3 = __float2half_rn(x.w);
    ((__half2*)(hi + i))[0] = __halves2half2(h0, h1);
    ((__half2*)(hi + i))[1] = __halves2half2(h2, h3);
    if (lo) {
        ((__half2*)(lo + i))[0] = __halves2half2(__float2half_rn(x.x - __half2float(h0)),
                                                 __float2half_rn(x.y - __half2float(h1)));
        ((__half2*)(lo + i))[1] = __halves2half2(__float2half_rn(x.z - __half2float(h2)),
                                                 __float2half_rn(x.w - __half2float(h3)));
    }
}

// ----------------------------------------------------------------------------
// Mask pre-pass
// ----------------------------------------------------------------------------
__global__ void __launch_bounds__(128) mask_any_kernel(const unsigned char* __restrict__ mask) {
    int jt = blockIdx.x, qt = blockIdx.y, b = blockIdx.z;
    const unsigned char* base = mask + ((size_t)b*SEQ + qt*64) * SEQ + jt*64;
    int t = threadIdx.x;
    unsigned int acc = 0;
    #pragma unroll
    for (int i = 0; i < 2; i++) {
        int idx = t + i*128;
        int row = idx >> 2, col = (idx & 3) * 16;
        uint4 x = *(const uint4*)(base + (size_t)row * SEQ + col);
        acc |= x.x | x.y | x.z | x.w;
    }
    int any = __syncthreads_or(acc != 0u);
    if (t == 0) g_mflag[(b*32 + qt)*32 + jt] = any ? 1 : 0;
}

// ----------------------------------------------------------------------------
// GEMM: 128x128 tile, 256 thr, k-step 32, NT terms (1: A*Whi; 2: +A*Wlo),
// 3-stage cp.async ring, one sync per k-step.
// Stage layout (bytes): Ah 0, Bh 10240, Bl 20480 (NT=2 only).
// ----------------------------------------------------------------------------
template<int NT>
__device__ __forceinline__ void gemm_stage_load(
    uint32_t sb, const __half* Agh, const __half* Bgh, const __half* Bgl,
    int m0, int n0, int k0, int t)
{
    #pragma unroll
    for (int i = 0; i < 2; i++) {
        int idx = t + i*256;
        int row = idx >> 2, col = (idx & 3) * 8;
        uint32_t so = (uint32_t)((row*40 + col) * 2);
        size_t ga = (size_t)(m0 + row) * HID + k0 + col;
        size_t gb = (size_t)(n0 + row) * HID + k0 + col;
        cpa(sb +         so, Agh + ga);
        cpa(sb + 10240 + so, Bgh + gb);
        if (NT == 2) cpa(sb + 20480 + so, Bgl + gb);
    }
    asm volatile("cp.async.commit_group;");
}

#define GEMM_MAINLOOP(NT, STG, Agh_, Bgh_, Bgl_)                                     \
    uint32_t smu = sm32(dsm);                                                        \
    gemm_stage_load<NT>(smu,       Agh_, Bgh_, Bgl_, m0, n0, 0,  t);                 \
    gemm_stage_load<NT>(smu + STG, Agh_, Bgh_, Bgl_, m0, n0, 32, t);                 \
    for (int ks = 0; ks < NKSTEP; ks++) {                                            \
        if (ks + 1 < NKSTEP) asm volatile("cp.async.wait_group 1;");                 \
        else                 asm volatile("cp.async.wait_group 0;");                 \
        __syncthreads();                                                             \
        if (ks + 2 < NKSTEP)                                                         \
            gemm_stage_load<NT>(smu + ((ks+2)%3)*STG, Agh_, Bgh_, Bgl_,              \
                                m0, n0, (ks+2)*32, t);                               \
        {                                                                            \
            char* stg = dsm + (ks % 3) * STG;                                        \
            __half* Ah = (__half*)stg;                                               \
            __half* Bh = (__half*)(stg + 10240);                                     \
            __half* Bl = (__half*)(stg + 20480);                                     \
            _Pragma("unroll")                                                        \
            for (int kk = 0; kk < 32; kk += 16) {                                    \
                wmma::fragment<wmma::matrix_a,16,16,16,__half,wmma::row_major> ah2[2]; \
                _Pragma("unroll")                                                    \
                for (int mi = 0; mi < 2; mi++)                                       \
                    wmma::load_matrix_sync(ah2[mi], Ah + (wm*32 + mi*16)*40 + kk, 40); \
                _Pragma("unroll")                                                    \
                for (int j = 0; j < 4; j++) {                                        \
                    wmma::fragment<wmma::matrix_b,16,16,16,__half,wmma::col_major> bh2; \
                    wmma::load_matrix_sync(bh2, Bh + (wn*64 + j*16)*40 + kk, 40);    \
                    _Pragma("unroll")                                                \
                    for (int mi = 0; mi < 2; mi++)                                   \
                        wmma::mma_sync(acc[mi][j], ah2[mi], bh2, acc[mi][j]);        \
                    if (NT == 2) {                                                   \
                        wmma::fragment<wmma::matrix_b,16,16,16,__half,wmma::col_major> bl2; \
                        wmma::load_matrix_sync(bl2, Bl + (wn*64 + j*16)*40 + kk, 40);\
                        _Pragma("unroll")                                            \
                        for (int mi = 0; mi < 2; mi++)                               \
                            wmma::mma_sync(acc[mi][j], ah2[mi], bl2, acc[mi][j]);    \
                    }                                                                \
                }                                                                    \
            }                                                                        \
        }                                                                            \
    }

// ----------------------------------------------------------------------------
// QKV projection. Epilogue writes hi to [b,h,s,d].
// ----------------------------------------------------------------------------
template<int NT>
__global__ void __launch_bounds__(256,2) proj_gemm_t(int zbase) {
    constexpr int STG = (NT == 2) ? 30720 : 20480;
    extern __shared__ __align__(16) char dsm[];
    int z = zbase + blockIdx.z;
    const __half* Agh = g_Xhi[z];
    const __half* Bgh = g_Whi[z]; const __half* Bgl = g_Wlo[z];
    __half* Ohi = g_QKVhi[z];

    int m0 = blockIdx.x * 128, n0 = blockIdx.y * 128;
    int t = threadIdx.x, w = t >> 5;
    int wm = w & 3, wn = w >> 2;

    wmma::fragment<wmma::accumulator,16,16,16,float> acc[2][4];
    #pragma unroll
    for (int mi = 0; mi < 2; mi++)
        #pragma unroll
        for (int j = 0; j < 4; j++) wmma::fill_fragment(acc[mi][j], 0.0f);

    GEMM_MAINLOOP(NT, STG, Agh, Bgh, Bgl)
    __syncthreads();

    float* Cs = (float*)dsm;  // 128x132 overlay = 67,584 B
    #pragma unroll
    for (int mi = 0; mi < 2; mi++)
        #pragma unroll
        for (int j = 0; j < 4; j++)
            wmma::store_matrix_sync(Cs + (wm*32 + mi*16)*132 + wn*64 + j*16,
                                    acc[mi][j], 132, wmma::mem_row_major);
    __syncthreads();

    for (int i = 0; i < 64; i++) {
        int idx = t + i*256; int r = idx >> 7; int c = idx & 127;
        float v0 = Cs[r*132 + c];
        int head = blockIdx.y*2 + (c >> 6); int d = c & 63;
        int rg = m0 + r; int b = rg >> 11; int s = rg & (SEQ-1);
        size_t o = (((size_t)b * NHEADS + head) * SEQ + s) * DK + d;
        Ohi[o] = __float2half_rn(v0);
    }
}

// ----------------------------------------------------------------------------
// Output projection (2-term), fp32 direct store
// ----------------------------------------------------------------------------
__global__ void __launch_bounds__(256,2) oproj_gemm_kernel(float* __restrict__ out) {
    constexpr int STG = 30720;
    extern __shared__ __align__(16) char dsm[];
    const __half* Agh = g_AOhi;
    const __half* Bgh = g_Whi[3]; const __half* Bgl = g_Wlo[3];

    int m0 = blockIdx.x * 128, n0 = blockIdx.y * 128;
    int t = threadIdx.x, w = t >> 5;
    int wm = w & 3, wn = w >> 2;

    wmma::fragment<wmma::accumulator,16,16,16,float> acc[2][4];
    #pragma unroll
    for (int mi = 0; mi < 2; mi++)
        #pragma unroll
        for (int j = 0; j < 4; j++) wmma::fill_fragment(acc[mi][j], 0.0f);

    GEMM_MAINLOOP(2, STG, Agh, Bgh, Bgl)

    #pragma unroll
    for (int mi = 0; mi < 2; mi++)
        #pragma unroll
        for (int j = 0; j < 4; j++)
            wmma::store_matrix_sync(out + (size_t)(m0 + wm*32 + mi*16) * HID + n0 + wn*64 + j*16,
                                    acc[mi][j], HID, wmma::mem_row_major);
}

// ----------------------------------------------------------------------------
// Flash attention: fp16 everywhere, ex2.approx.f16x2 softmax,
// row sums via ones-column MMA, cp.async double-buffered K/V.
// ----------------------------------------------------------------------------
__global__ void __launch_bounds__(128,3) attn_kernel(const unsigned char* __restrict__ mask) {
    __shared__ __align__(16) __half KV[2][2][64*72];   // [stage][K=0/V=1]
    __shared__ __align__(16) unsigned char Msk[64*64];

    int t = threadIdx.x, lane = t & 31, w = t >> 5;
    int gr = lane >> 2, qp = lane & 3;
    int qt = blockIdx.x, hd = blockIdx.y, b = blockIdx.z;
    int q0 = qt * 64;
    size_t base = ((size_t)b * NHEADS + hd) * SEQ;
    const __half* Qh_g = g_QKVhi[0] + (base + q0) * DK;
    const __half* Kh_g = g_QKVhi[1] + base * DK;
    const __half* Vh_g = g_QKVhi[2] + base * DK;

    int r0 = w*16 + gr;
    int r1 = r0 + 8;

    const __half2 sc = __float2half2_rn(0.125f);  // 1/sqrt(64), exact pow2
    uint32_t qa[4][4];
    #pragma unroll
    for (int kc = 0; kc < 4; kc++) {
        int cb = kc*16 + qp*2;
        __half2 v;
        v = __hmul2(*(const __half2*)(Qh_g + r0*DK + cb),     sc); qa[kc][0] = *(uint32_t*)&v;
        v = __hmul2(*(const __half2*)(Qh_g + r1*DK + cb),     sc); qa[kc][1] = *(uint32_t*)&v;
        v = __hmul2(*(const __half2*)(Qh_g + r0*DK + cb + 8), sc); qa[kc][2] = *(uint32_t*)&v;
        v = __hmul2(*(const __half2*)(Qh_g + r1*DK + cb + 8), sc); qa[kc][3] = *(uint32_t*)&v;
    }

    float o[8][4];
    #pragma unroll
    for (int n = 0; n < 8; n++) { o[n][0]=0.f; o[n][1]=0.f; o[n][2]=0.f; o[n][3]=0.f; }
    float osum[4] = {0.f, 0.f, 0.f, 0.f};          // row-sum accumulator (ones column)
    float m0v = -1e30f, m1v = -1e30f;
    const uint32_t ones2[2] = {0x3C003C00u, 0x3C003C00u};
    const float LOG2E = 1.44269504f;

    const unsigned char* flagrow = g_mflag + (b*32 + qt)*32;

    auto load_stage = [&](int jt, int stg) {
        #pragma unroll
        for (int i = 0; i < 4; i++) {
            int idx = t + i*128; int row = idx >> 3; int col = (idx & 7) * 8;
            size_t g = (size_t)(jt*64 + row) * DK + col;
            cpa(sm32(&KV[stg][0][row*72 + col]), Kh_g + g);
            cpa(sm32(&KV[stg][1][row*72 + col]), Vh_g + g);
        }
        asm volatile("cp.async.commit_group;");
    };

    load_stage(0, 0);

    for (int jt = 0; jt < SEQ/64; jt++) {
        int stg = jt & 1;
        if (jt + 1 < SEQ/64) {
            load_stage(jt+1, stg ^ 1);
            asm volatile("cp.async.wait_group 1;");
        } else {
            asm volatile("cp.async.wait_group 0;");
        }
        __syncthreads();

        int anym = flagrow[jt];
        if (anym) {
            #pragma unroll
            for (int i = 0; i < 2; i++) {
                int idx = t + i*128; int rl = idx >> 2, cl = (idx & 3) * 16;
                *(uint4*)(Msk + rl*64 + cl) =
                    *(const uint4*)(mask + ((size_t)b*SEQ + q0 + rl) * SEQ + jt*64 + cl);
            }
            __syncthreads();
        }

        __half* Kh = KV[stg][0];
        __half* Vh = KV[stg][1];

        // S = Q@K^T
        float s[8][4];
        #pragma unroll
        for (int n = 0; n < 8; n++) { s[n][0]=0.f; s[n][1]=0.f; s[n][2]=0.f; s[n][3]=0.f; }
        #pragma unroll
        for (int kc = 0; kc < 4; kc++) {
            #pragma unroll
            for (int np = 0; np < 4; np++) {
                int j = np*16 + (lane & 7) + ((lane >> 4) << 3);
                int d = kc*16 + ((lane >> 3) & 1) * 8;
                uint32_t kh4[4];
                ldsm_x4(kh4, sm32(Kh + j*72 + d));
                mma_f16(s[2*np],   qa[kc], kh4);
                mma_f16(s[2*np+1], qa[kc], kh4+2);
            }
        }

        if (anym) {
            const unsigned char* mr0 = Msk + r0*64;
            const unsigned char* mr1 = Msk + r1*64;
            #pragma unroll
            for (int n = 0; n < 8; n++) {
                #pragma unroll
                for (int e = 0; e < 2; e++) {
                    int c = n*8 + qp*2 + e;
                    if (mr0[c]) s[n][e]   = -1e9f;
                    if (mr1[c]) s[n][2+e] = -1e9f;
                }
            }
        }

        // warp-local online max
        float mx0 = -1e30f, mx1 = -1e30f;
        #pragma unroll
        for (int n = 0; n < 8; n++) {
            mx0 = fmaxf(mx0, fmaxf(s[n][0], s[n][1]));
            mx1 = fmaxf(mx1, fmaxf(s[n][2], s[n][3]));
        }
        mx0 = fmaxf(mx0, __shfl_xor_sync(0xffffffffu, mx0, 1));
        mx0 = fmaxf(mx0, __shfl_xor_sync(0xffffffffu, mx0, 2));
        mx1 = fmaxf(mx1, __shfl_xor_sync(0xffffffffu, mx1, 1));
        mx1 = fmaxf(mx1, __shfl_xor_sync(0xffffffffu, mx1, 2));
        float mn0 = fmaxf(m0v, mx0), mn1 = fmaxf(m1v, mx1);

        // P = 2^((s-m)*log2e) directly into fp16x2 fragments
        float c0 = mn0 * LOG2E, c1 = mn1 * LOG2E;
        uint32_t pa[4][4];
        #pragma unroll
        for (int n = 0; n < 8; n++) {
            float t0 = __fmaf_rn(s[n][0], LOG2E, -c0);
            float t1 = __fmaf_rn(s[n][1], LOG2E, -c0);
            float t2 = __fmaf_rn(s[n][2], LOG2E, -c1);
            float t3 = __fmaf_rn(s[n][3], LOG2E, -c1);
            int kc = n >> 1, h = (n & 1) * 2;
            pa[kc][h]     = ex2h2(t0, t1);
            pa[kc][h + 1] = ex2h2(t2, t3);
        }

        float ef0 = __expf(m0v - mn0), ef1 = __expf(m1v - mn1);
        m0v = mn0; m1v = mn1;
        #pragma unroll
        for (int n = 0; n < 8; n++) {
            o[n][0] *= ef0; o[n][1] *= ef0; o[n][2] *= ef1; o[n][3] *= ef1;
        }
        osum[0] *= ef0; osum[1] *= ef0; osum[2] *= ef1; osum[3] *= ef1;

        // O += P @ V ; row sums += P @ ones
        #pragma unroll
        for (int kc = 0; kc < 4; kc++) {
            mma_f16(osum, pa[kc], ones2);
            #pragma unroll
            for (int dp = 0; dp < 4; dp++) {
                int j = kc*16 + (lane & 7) + (((lane >> 3) & 1) << 3);
                int d = dp*16 + ((lane >> 4) << 3);
                uint32_t vh4[4];
                ldsm_x4_t(vh4, sm32(Vh + j*72 + d));
                mma_f16(o[2*dp],   pa[kc], vh4);
                mma_f16(o[2*dp+1], pa[kc], vh4+2);
            }
        }
        __syncthreads();
    }

    // Epilogue: normalize (osum[0]=row r0 sum, osum[2]=row r1 sum in every lane)
    float inv0 = 1.0f / osum[0], inv1 = 1.0f / osum[2];
    #pragma unroll
    for (int n = 0; n < 8; n++) {
        int col = n*8 + qp*2;
        float a0 = o[n][0]*inv0, a1 = o[n][1]*inv0;
        float b0 = o[n][2]*inv1, b1 = o[n][3]*inv1;
        size_t off0 = ((size_t)b*SEQ + q0 + r0) * HID + hd*DK + col;
        size_t off1 = ((size_t)b*SEQ + q0 + r1) * HID + hd*DK + col;
        *(__half2*)(g_AOhi + off0) = __floats2half2_rn(a0, a1);
        *(__half2*)(g_AOhi + off1) = __floats2half2_rn(b0, b1);
    }
}

// ----------------------------------------------------------------------------
// Launch
// ----------------------------------------------------------------------------
extern "C" void kernel_launch(void* const* d_in, const int* in_sizes, int n_in,
                              void* d_out, int out_size) {
    const float* q    = (const float*)d_in[0];
    const float* k    = (const float*)d_in[1];
    const float* v    = (const float*)d_in[2];
    const unsigned char* mask = (const unsigned char*)d_in[3];
    const float* Wq   = (const float*)d_in[4];
    const float* Wk   = (const float*)d_in[5];
    const float* Wv   = (const float*)d_in[6];
    const float* Wo   = (const float*)d_in[7];
    float* out = (float*)d_out;

    const int SM1 = 67584;          // max(3*20480, Cs overlay)
    const int SM2 = 3*30720;        // 92160 (>= overlay)
    cudaFuncSetAttribute(proj_gemm_t<1>,   cudaFuncAttributeMaxDynamicSharedMemorySize, SM1);
    cudaFuncSetAttribute(proj_gemm_t<2>,   cudaFuncAttributeMaxDynamicSharedMemorySize, SM2);
    cudaFuncSetAttribute(oproj_gemm_kernel,cudaFuncAttributeMaxDynamicSharedMemorySize, SM2);

    f2hl_all<<<dim3(MTOT*HID/(256*4), 7), 256>>>(q, k, v, Wq, Wk, Wv, Wo);
    mask_any_kernel<<<dim3(32, 32, BATCH), 128>>>(mask);
    proj_gemm_t<1><<<dim3(MTOT/128, HID/128, 2), 256, SM1>>>(0);   // Q, K (plain fp16)
    proj_gemm_t<2><<<dim3(MTOT/128, HID/128, 1), 256, SM2>>>(2);   // V (weight-compensated)
    attn_kernel<<<dim3(SEQ/64, NHEADS, BATCH), 128>>>(mask);
    oproj_gemm_kernel<<<dim3(MTOT/128, HID/128), 256, SM2>>>(out);
}